// round 9
// baseline (speedup 1.0000x reference)
#include <cuda_runtime.h>
#include <cuda_bf16.h>
#include <cstdint>

#define NN 100000
#define EE 640000
#define EP 740000            /* EE + NN self loops */
#define CC 128
#define NEG_SLOPE 0.2f
#define SCAN_BLK 1024
#define NBLK ((NN + SCAN_BLK - 1) / SCAN_BLK)   /* 98 */

// ---------------- device scratch ---------------------------------------------
__device__ __align__(16) float g_xl[(size_t)NN * CC];
__device__ __align__(16) float g_xr[(size_t)NN * CC];
__device__ __align__(16) float g_h [(size_t)NN * CC];
__device__ __align__(16) __nv_bfloat16 g_Wh[6 * CC * CC];  // weights hi (bf16)
__device__ __align__(16) __nv_bfloat16 g_Wl[6 * CC * CC];  // weights lo (bf16)
__device__ int   g_deg[NN];
__device__ int   g_cur[NN];
__device__ int   g_off[NN];
__device__ int   g_bsum[NBLK];
__device__ int   g_csr[EP];

// ---------------- weight pre-split (fp32 -> bf16 hi/lo) -----------------------
__global__ void wsplit_kernel(const float* __restrict__ W0, const float* __restrict__ W1,
                              const float* __restrict__ W2, const float* __restrict__ W3,
                              const float* __restrict__ W4, const float* __restrict__ W5)
{
    const float* Ws[6] = {W0, W1, W2, W3, W4, W5};
    int i = blockIdx.x * blockDim.x + threadIdx.x;
    if (i >= 6 * CC * CC) return;
    float v = Ws[i >> 14][i & 16383];
    __nv_bfloat16 h = __float2bfloat16(v);
    __nv_bfloat16 l = __float2bfloat16(v - __bfloat162float(h));
    g_Wh[i] = h;
    g_Wl[i] = l;
}

// ---------------- CSR build ---------------------------------------------------
__global__ void hist_kernel(const int* __restrict__ ei) {
    int e = blockIdx.x * blockDim.x + threadIdx.x;
    if (e >= EP) return;
    int d = (e < EE) ? ei[EE + e] : (e - EE);
    atomicAdd(&g_deg[d], 1);
}

__global__ void scan1_kernel() {
    __shared__ int sh[SCAN_BLK];
    int i = blockIdx.x * SCAN_BLK + threadIdx.x;
    int v = (i < NN) ? g_deg[i] : 0;
    sh[threadIdx.x] = v;
    __syncthreads();
    for (int o = 1; o < SCAN_BLK; o <<= 1) {
        int t = (threadIdx.x >= o) ? sh[threadIdx.x - o] : 0;
        __syncthreads();
        sh[threadIdx.x] += t;
        __syncthreads();
    }
    if (i < NN) g_off[i] = sh[threadIdx.x] - v;
    if (threadIdx.x == SCAN_BLK - 1) g_bsum[blockIdx.x] = sh[threadIdx.x];
}

__global__ void scan2_kernel() {
    __shared__ int sh[128];
    int b = threadIdx.x;
    int v = (b < NBLK) ? g_bsum[b] : 0;
    sh[b] = v;
    __syncthreads();
    for (int o = 1; o < 128; o <<= 1) {
        int t = (b >= o) ? sh[b - o] : 0;
        __syncthreads();
        sh[b] += t;
        __syncthreads();
    }
    if (b < NBLK) g_bsum[b] = sh[b] - v;
}

__global__ void scan3_kernel() {
    int i = blockIdx.x * blockDim.x + threadIdx.x;
    if (i < NN) g_off[i] += g_bsum[i / SCAN_BLK];
}

__global__ void scatter_kernel(const int* __restrict__ ei) {
    int e = blockIdx.x * blockDim.x + threadIdx.x;
    if (e >= EP) return;
    int s, d;
    if (e < EE) { s = ei[e]; d = ei[EE + e]; }
    else        { s = d = e - EE; }
    int pos = g_off[d] + atomicAdd(&g_cur[d], 1);
    g_csr[pos] = s;
}

// ================= HMMA (mma.sync) 3-output GEMM ==============================
// out_j[n][c] = b_j[c] + sum_k f(x[n][k]) * W_j[c][k]
// fp32 split hi+lo bf16; D = Ah*Bh + Ah*Bl + Al*Bh (lo*lo dropped, ~2^-18 rel).
// CTA tile M=64 x N=128 (was 128x128): smem 104.4 KB -> 2 CTAs/SM, occ 25%
// (R8 profile: occ=12.5%, tensor=40% -> latency-bound at 1 CTA/SM).
// 8 warps = 2(m)x4(n) warp tiles of 32x32. W pre-split in gmem.
#define MT 64                            /* CTA rows */
#define AS_STRIDE 136                    /* bf16 units, even & bank-clean */
#define A_TILE_B (MT * AS_STRIDE * 2)    /* 17408 */
#define B_TILE_B (128 * AS_STRIDE * 2)   /* 34816 */
#define SM_AHI 0
#define SM_ALO (A_TILE_B)
#define SM_BHI (2 * A_TILE_B)
#define SM_BLO (2 * A_TILE_B + B_TILE_B)
#define SM_TOTAL (2 * A_TILE_B + 2 * B_TILE_B)   /* 104448 */

__device__ __forceinline__ void mma16816(float* c, const uint32_t* a,
                                         const uint32_t* b) {
    asm volatile(
        "mma.sync.aligned.m16n8k16.row.col.f32.bf16.bf16.f32 "
        "{%0,%1,%2,%3}, {%4,%5,%6,%7}, {%8,%9}, {%0,%1,%2,%3};"
        : "+f"(c[0]), "+f"(c[1]), "+f"(c[2]), "+f"(c[3])
        : "r"(a[0]), "r"(a[1]), "r"(a[2]), "r"(a[3]), "r"(b[0]), "r"(b[1]));
}

__device__ __forceinline__ void cvt_pair(char* hi, char* lo, int row, int k,
                                         float a, float b) {
    __nv_bfloat16 h0 = __float2bfloat16(a), h1 = __float2bfloat16(b);
    __nv_bfloat16 l0 = __float2bfloat16(a - __bfloat162float(h0));
    __nv_bfloat16 l1 = __float2bfloat16(b - __bfloat162float(h1));
    uint32_t hw = (uint32_t)__bfloat16_as_ushort(h0)
                | ((uint32_t)__bfloat16_as_ushort(h1) << 16);
    uint32_t lw = (uint32_t)__bfloat16_as_ushort(l0)
                | ((uint32_t)__bfloat16_as_ushort(l1) << 16);
    uint32_t off = (uint32_t)(row * AS_STRIDE + k) * 2;
    *(uint32_t*)(hi + off) = hw;
    *(uint32_t*)(lo + off) = lw;
}

__device__ __forceinline__ void load_a_split(const float* src, int nrows,
                                             int relu, char* hi, char* lo,
                                             int tid) {
#pragma unroll
    for (int t = 0; t < 8; t++) {
        int idx = tid + t * 256;         // 2048 float4 total (64 rows x 32)
        int row = idx >> 5;
        int k4  = (idx & 31) << 2;
        float4 v = make_float4(0.f, 0.f, 0.f, 0.f);
        if (row < nrows) v = *(const float4*)(src + (size_t)row * CC + k4);
        if (relu) {
            v.x = fmaxf(v.x, 0.f); v.y = fmaxf(v.y, 0.f);
            v.z = fmaxf(v.z, 0.f); v.w = fmaxf(v.w, 0.f);
        }
        cvt_pair(hi, lo, row, k4,     v.x, v.y);
        cvt_pair(hi, lo, row, k4 + 2, v.z, v.w);
    }
}

// copy pre-split bf16 W tile [128][128] row-major -> smem stride AS_STRIDE
__device__ __forceinline__ void copy_w_tile(const __nv_bfloat16* src, char* dst,
                                            int tid) {
#pragma unroll
    for (int t = 0; t < 8; t++) {
        int idx = tid + t * 256;         // 2048 uint4 (8 bf16 each)
        int row = idx >> 4;
        int k8  = (idx & 15) << 3;
        uint4 v = *(const uint4*)(src + row * CC + k8);
        *(uint4*)(dst + (uint32_t)(row * AS_STRIDE + k8) * 2) = v;
    }
}

__global__ __launch_bounds__(256, 2) void gemm3_tc_kernel(
    const float* __restrict__ x,
    const __nv_bfloat16* __restrict__ Wh, const __nv_bfloat16* __restrict__ Wl,
    int mat0,
    const float* __restrict__ b0, float* __restrict__ o0,
    const float* __restrict__ b1, float* __restrict__ o1,
    const float* __restrict__ b2, float* __restrict__ o2,
    int relu_in)
{
    extern __shared__ char sm[];
    const int tid  = threadIdx.x;
    const int wid  = tid >> 5;
    const int lane = tid & 31;
    const int g    = lane >> 2;          // 0..7
    const int tg   = lane & 3;           // 0..3
    const int row0 = blockIdx.x * MT;
    const int nrows = (NN - row0 < MT) ? (NN - row0) : MT;
    const int wm0 = (wid >> 2) * 32;     // warp tile m origin (0 / 32)
    const int wn0 = (wid & 3) * 32;      // warp tile n origin (0/32/64/96)

    // A tile -> bf16 hi/lo (once)
    load_a_split(x + (size_t)row0 * CC, nrows, relu_in,
                 sm + SM_AHI, sm + SM_ALO, tid);

    const float* bs[3] = {b0, b1, b2};
    float*       os[3] = {o0, o1, o2};

    const __nv_bfloat16* Ah = (const __nv_bfloat16*)(sm + SM_AHI);
    const __nv_bfloat16* Al = (const __nv_bfloat16*)(sm + SM_ALO);
    const __nv_bfloat16* Bh = (const __nv_bfloat16*)(sm + SM_BHI);
    const __nv_bfloat16* Bl = (const __nv_bfloat16*)(sm + SM_BLO);

    for (int j = 0; j < 3; j++) {
        __syncthreads();                 // previous Bs fully consumed
        copy_w_tile(Wh + (size_t)(mat0 + j) * CC * CC, sm + SM_BHI, tid);
        copy_w_tile(Wl + (size_t)(mat0 + j) * CC * CC, sm + SM_BLO, tid);
        __syncthreads();

        float acc[2][4][4];
#pragma unroll
        for (int ma = 0; ma < 2; ma++)
#pragma unroll
            for (int na = 0; na < 4; na++)
#pragma unroll
                for (int q = 0; q < 4; q++) acc[ma][na][q] = 0.f;

#pragma unroll
        for (int ks = 0; ks < 8; ks++) {
            const int kb = ks * 16 + tg * 2;     // bf16 col of pair
            uint32_t bh[4][2], bl[4][2], af[2][4];
#pragma unroll
            for (int na = 0; na < 4; na++) {
                int n = wn0 + na * 8 + g;
                bh[na][0] = *(const uint32_t*)(Bh + n * AS_STRIDE + kb);
                bh[na][1] = *(const uint32_t*)(Bh + n * AS_STRIDE + kb + 8);
                bl[na][0] = *(const uint32_t*)(Bl + n * AS_STRIDE + kb);
                bl[na][1] = *(const uint32_t*)(Bl + n * AS_STRIDE + kb + 8);
            }
            // A_hi fragments
#pragma unroll
            for (int ma = 0; ma < 2; ma++) {
                int m = wm0 + ma * 16 + g;
                af[ma][0] = *(const uint32_t*)(Ah + m * AS_STRIDE + kb);
                af[ma][1] = *(const uint32_t*)(Ah + (m + 8) * AS_STRIDE + kb);
                af[ma][2] = *(const uint32_t*)(Ah + m * AS_STRIDE + kb + 8);
                af[ma][3] = *(const uint32_t*)(Ah + (m + 8) * AS_STRIDE + kb + 8);
            }
#pragma unroll
            for (int ma = 0; ma < 2; ma++)
#pragma unroll
                for (int na = 0; na < 4; na++)
                    mma16816(acc[ma][na], af[ma], bh[na]);
#pragma unroll
            for (int ma = 0; ma < 2; ma++)
#pragma unroll
                for (int na = 0; na < 4; na++)
                    mma16816(acc[ma][na], af[ma], bl[na]);
            // A_lo fragments (reuse af regs)
#pragma unroll
            for (int ma = 0; ma < 2; ma++) {
                int m = wm0 + ma * 16 + g;
                af[ma][0] = *(const uint32_t*)(Al + m * AS_STRIDE + kb);
                af[ma][1] = *(const uint32_t*)(Al + (m + 8) * AS_STRIDE + kb);
                af[ma][2] = *(const uint32_t*)(Al + m * AS_STRIDE + kb + 8);
                af[ma][3] = *(const uint32_t*)(Al + (m + 8) * AS_STRIDE + kb + 8);
            }
#pragma unroll
            for (int ma = 0; ma < 2; ma++)
#pragma unroll
                for (int na = 0; na < 4; na++)
                    mma16816(acc[ma][na], af[ma], bh[na]);
        }

        // epilogue: bias + direct gmem stores (float2 per atom-half)
        const float* bias = bs[j];
        float* o = os[j];
#pragma unroll
        for (int na = 0; na < 4; na++) {
            int col = wn0 + na * 8 + tg * 2;
            float2 bb = *(const float2*)(bias + col);
#pragma unroll
            for (int ma = 0; ma < 2; ma++) {
                int ra = row0 + wm0 + ma * 16 + g;
                if (ra < NN) {
                    float2 v = make_float2(acc[ma][na][0] + bb.x,
                                           acc[ma][na][1] + bb.y);
                    *(float2*)(o + (size_t)ra * CC + col) = v;
                }
                int rb = ra + 8;
                if (rb < NN) {
                    float2 v = make_float2(acc[ma][na][2] + bb.x,
                                           acc[ma][na][3] + bb.y);
                    *(float2*)(o + (size_t)rb * CC + col) = v;
                }
            }
        }
    }
}

// ---------------- fused attention + aggregation (warp per dst, no atomics) ---
// 2-edge unroll: two independent shuffle-reduce chains in flight (ILP=2).
__device__ __forceinline__ float leaky_dot(float4 a, float4 r, float4 t) {
    float4 m;
    m.x = a.x + r.x; m.x = m.x > 0.f ? m.x : NEG_SLOPE * m.x;
    m.y = a.y + r.y; m.y = m.y > 0.f ? m.y : NEG_SLOPE * m.y;
    m.z = a.z + r.z; m.z = m.z > 0.f ? m.z : NEG_SLOPE * m.z;
    m.w = a.w + r.w; m.w = m.w > 0.f ? m.w : NEG_SLOPE * m.w;
    float p = m.x * t.x;
    p = fmaf(m.y, t.y, p);
    p = fmaf(m.z, t.z, p);
    p = fmaf(m.w, t.w, p);
    return p;
}

__global__ __launch_bounds__(256) void aggr_kernel(
    const float* __restrict__ xl, const float* __restrict__ xr,
    const float* __restrict__ att, float* __restrict__ res_out)
{
    int gw   = (int)((blockIdx.x * 256u + threadIdx.x) >> 5);
    int lane = threadIdx.x & 31;
    if (gw >= NN) return;
    const int d = gw;

    float4 t = *(const float4*)(att + lane * 4);
    float4 r = *(const float4*)(xr + (size_t)d * CC + lane * 4);

    const int start = g_off[d];
    const int deg   = g_deg[d];          // >= 1 (self loop)

    float denom = 0.f;
    float4 acc = make_float4(0.f, 0.f, 0.f, 0.f);

    int jj = 0;
    for (; jj + 1 < deg; jj += 2) {
        int s0 = g_csr[start + jj];
        int s1 = g_csr[start + jj + 1];
        float4 a0 = *(const float4*)(xl + (size_t)s0 * CC + lane * 4);
        float4 a1 = *(const float4*)(xl + (size_t)s1 * CC + lane * 4);
        float p0 = leaky_dot(a0, r, t);
        float p1 = leaky_dot(a1, r, t);
#pragma unroll
        for (int off = 16; off > 0; off >>= 1) {
            p0 += __shfl_xor_sync(0xffffffffu, p0, off);
            p1 += __shfl_xor_sync(0xffffffffu, p1, off);
        }
        float ev0 = expf(p0);
        float ev1 = expf(p1);
        denom += ev0 + ev1;
        acc.x = fmaf(ev0, a0.x, fmaf(ev1, a1.x, acc.x));
        acc.y = fmaf(ev0, a0.y, fmaf(ev1, a1.y, acc.y));
        acc.z = fmaf(ev0, a0.z, fmaf(ev1, a1.z, acc.z));
        acc.w = fmaf(ev0, a0.w, fmaf(ev1, a1.w, acc.w));
    }
    if (jj < deg) {
        int s0 = g_csr[start + jj];
        float4 a0 = *(const float4*)(xl + (size_t)s0 * CC + lane * 4);
        float p0 = leaky_dot(a0, r, t);
#pragma unroll
        for (int off = 16; off > 0; off >>= 1)
            p0 += __shfl_xor_sync(0xffffffffu, p0, off);
        float ev0 = expf(p0);
        denom += ev0;
        acc.x = fmaf(ev0, a0.x, acc.x);
        acc.y = fmaf(ev0, a0.y, acc.y);
        acc.z = fmaf(ev0, a0.z, acc.z);
        acc.w = fmaf(ev0, a0.w, acc.w);
    }

    float inv = 1.f / denom;
    float* op = res_out + (size_t)d * CC + lane * 4;
    float4 rr = *(const float4*)op;
    float4 o = make_float4(fmaf(acc.x, inv, rr.x), fmaf(acc.y, inv, rr.y),
                           fmaf(acc.z, inv, rr.z), fmaf(acc.w, inv, rr.w));
    *(float4*)op = o;
}

// ---------------- launch ------------------------------------------------------
extern "C" void kernel_launch(void* const* d_in, const int* in_sizes, int n_in,
                              void* d_out, int out_size)
{
    const int*   ei    = (const int*)  d_in[0];
    const float* emb   = (const float*)d_in[1];
    const float* Wl1   = (const float*)d_in[2];
    const float* bl1   = (const float*)d_in[3];
    const float* Wr1   = (const float*)d_in[4];
    const float* br1   = (const float*)d_in[5];
    const float* att1  = (const float*)d_in[6];
    const float* Wres1 = (const float*)d_in[7];
    const float* bias1 = (const float*)d_in[8];
    const float* Wl2   = (const float*)d_in[9];
    const float* bl2   = (const float*)d_in[10];
    const float* Wr2   = (const float*)d_in[11];
    const float* br2   = (const float*)d_in[12];
    const float* att2  = (const float*)d_in[13];
    const float* Wres2 = (const float*)d_in[14];
    const float* bias2 = (const float*)d_in[15];
    float* out = (float*)d_out;

    float *xl, *xr, *h;
    __nv_bfloat16 *Wh, *Wl;
    int *deg, *cur;
    cudaGetSymbolAddress((void**)&xl,  g_xl);
    cudaGetSymbolAddress((void**)&xr,  g_xr);
    cudaGetSymbolAddress((void**)&h,   g_h);
    cudaGetSymbolAddress((void**)&Wh,  g_Wh);
    cudaGetSymbolAddress((void**)&Wl,  g_Wl);
    cudaGetSymbolAddress((void**)&deg, g_deg);
    cudaGetSymbolAddress((void**)&cur, g_cur);

    cudaFuncSetAttribute(gemm3_tc_kernel,
                         cudaFuncAttributeMaxDynamicSharedMemorySize, SM_TOTAL);

    const int edge_grid = (EP + 255) / 256;        // 2891
    const int gemm_grid = (NN + MT - 1) / MT;      // 1563
    const int aggr_grid = (NN * 32 + 255) / 256;   // 12500

    // Launch order chosen so ncu (-s 5 -c 1, memsets count) captures gemm3_tc.
    cudaMemsetAsync(deg, 0, NN * sizeof(int));                      // 0
    cudaMemsetAsync(cur, 0, NN * sizeof(int));                      // 1
    wsplit_kernel<<<(6 * CC * CC + 255) / 256, 256>>>(              // 2
        Wl1, Wr1, Wres1, Wl2, Wr2, Wres2);
    hist_kernel<<<edge_grid, 256>>>(ei);                            // 3
    scan1_kernel<<<NBLK, SCAN_BLK>>>();                             // 4
    gemm3_tc_kernel<<<gemm_grid, 256, SM_TOTAL>>>(                  // 5  <- profiled
        emb, Wh, Wl, 0, bl1, xl, br1, xr, bias1, h, 0);
    scan2_kernel<<<1, 128>>>();                                     // 6
    scan3_kernel<<<(NN + 255) / 256, 256>>>();                      // 7
    scatter_kernel<<<edge_grid, 256>>>(ei);                         // 8
    aggr_kernel<<<aggr_grid, 256>>>(xl, xr, att1, h);               // 9
    gemm3_tc_kernel<<<gemm_grid, 256, SM_TOTAL>>>(                  // 10
        h, Wh, Wl, 3, bl2, xl, br2, xr, bias2, out, 1);
    aggr_kernel<<<aggr_grid, 256>>>(xl, xr, att2, out);             // 11
}

// round 10
// speedup vs baseline: 1.3972x; 1.3972x over previous
#include <cuda_runtime.h>
#include <cuda_bf16.h>
#include <cstdint>

#define NN 100000
#define EE 640000
#define EP 740000            /* EE + NN self loops */
#define CC 128
#define NEG_SLOPE 0.2f
#define SCAN_BLK 1024
#define NBLK ((NN + SCAN_BLK - 1) / SCAN_BLK)   /* 98 */

// ---------------- device scratch ---------------------------------------------
__device__ __align__(16) float g_xl[(size_t)NN * CC];
__device__ __align__(16) float g_xr[(size_t)NN * CC];
__device__ __align__(16) float g_h [(size_t)NN * CC];
__device__ __align__(16) __nv_bfloat16 g_Wh[6 * CC * CC];  // weights hi (bf16)
__device__ __align__(16) __nv_bfloat16 g_Wl[6 * CC * CC];  // weights lo (bf16)
__device__ int   g_deg[NN];
__device__ int   g_cur[NN];
__device__ int   g_off[NN];
__device__ int   g_bsum[NBLK];
__device__ int   g_csr[EP];

// ---------------- weight pre-split (fp32 -> bf16 hi/lo) -----------------------
__global__ void wsplit_kernel(const float* __restrict__ W0, const float* __restrict__ W1,
                              const float* __restrict__ W2, const float* __restrict__ W3,
                              const float* __restrict__ W4, const float* __restrict__ W5)
{
    const float* Ws[6] = {W0, W1, W2, W3, W4, W5};
    int i = blockIdx.x * blockDim.x + threadIdx.x;
    if (i >= 6 * CC * CC) return;
    float v = Ws[i >> 14][i & 16383];
    __nv_bfloat16 h = __float2bfloat16(v);
    __nv_bfloat16 l = __float2bfloat16(v - __bfloat162float(h));
    g_Wh[i] = h;
    g_Wl[i] = l;
}

// ---------------- CSR build ---------------------------------------------------
__global__ void hist_kernel(const int* __restrict__ ei) {
    int e = blockIdx.x * blockDim.x + threadIdx.x;
    if (e >= EP) return;
    int d = (e < EE) ? ei[EE + e] : (e - EE);
    atomicAdd(&g_deg[d], 1);
}

__global__ void scan1_kernel() {
    __shared__ int sh[SCAN_BLK];
    int i = blockIdx.x * SCAN_BLK + threadIdx.x;
    int v = (i < NN) ? g_deg[i] : 0;
    sh[threadIdx.x] = v;
    __syncthreads();
    for (int o = 1; o < SCAN_BLK; o <<= 1) {
        int t = (threadIdx.x >= o) ? sh[threadIdx.x - o] : 0;
        __syncthreads();
        sh[threadIdx.x] += t;
        __syncthreads();
    }
    if (i < NN) g_off[i] = sh[threadIdx.x] - v;
    if (threadIdx.x == SCAN_BLK - 1) g_bsum[blockIdx.x] = sh[threadIdx.x];
}

__global__ void scan2_kernel() {
    __shared__ int sh[128];
    int b = threadIdx.x;
    int v = (b < NBLK) ? g_bsum[b] : 0;
    sh[b] = v;
    __syncthreads();
    for (int o = 1; o < 128; o <<= 1) {
        int t = (b >= o) ? sh[b - o] : 0;
        __syncthreads();
        sh[b] += t;
        __syncthreads();
    }
    if (b < NBLK) g_bsum[b] = sh[b] - v;
}

__global__ void scan3_kernel() {
    int i = blockIdx.x * blockDim.x + threadIdx.x;
    if (i < NN) g_off[i] += g_bsum[i / SCAN_BLK];
}

__global__ void scatter_kernel(const int* __restrict__ ei) {
    int e = blockIdx.x * blockDim.x + threadIdx.x;
    if (e >= EP) return;
    int s, d;
    if (e < EE) { s = ei[e]; d = ei[EE + e]; }
    else        { s = d = e - EE; }
    int pos = g_off[d] + atomicAdd(&g_cur[d], 1);
    g_csr[pos] = s;
}

// ================= HMMA (mma.sync) 3-output GEMM ==============================
// R8 config (M=128x128, 1 CTA/SM) + ldmatrix: R9 showed the limiter is LDS
// issue (L1 65%, occ-doubling regressed), so cut LDS instr 4x via LDSM.x4.
// fp32 split hi+lo bf16; D = Ah*Bh + Ah*Bl + Al*Bh (lo*lo dropped, ~2^-18).
// 8 warps = 2(m)x4(n) warp tiles of 64x32.
#define AS_STRIDE 136                    /* bf16 units; LDSM rows 272B apart -> banks 4r..4r+3, conflict-free */
#define TILE_B (128 * AS_STRIDE * 2)     /* 34816 bytes */
#define SM_AHI 0
#define SM_ALO (TILE_B)
#define SM_BHI (2 * TILE_B)
#define SM_BLO (3 * TILE_B)
#define SM_TOTAL (4 * TILE_B)            /* 139264 */

__device__ __forceinline__ void mma16816(float* c, const uint32_t* a,
                                         const uint32_t* b) {
    asm volatile(
        "mma.sync.aligned.m16n8k16.row.col.f32.bf16.bf16.f32 "
        "{%0,%1,%2,%3}, {%4,%5,%6,%7}, {%8,%9}, {%0,%1,%2,%3};"
        : "+f"(c[0]), "+f"(c[1]), "+f"(c[2]), "+f"(c[3])
        : "r"(a[0]), "r"(a[1]), "r"(a[2]), "r"(a[3]), "r"(b[0]), "r"(b[1]));
}

__device__ __forceinline__ void ldsm_x4(uint32_t* r, uint32_t addr) {
    asm volatile("ldmatrix.sync.aligned.m8n8.x4.shared.b16 {%0,%1,%2,%3}, [%4];"
                 : "=r"(r[0]), "=r"(r[1]), "=r"(r[2]), "=r"(r[3]) : "r"(addr));
}

__device__ __forceinline__ void cvt_pair(char* hi, char* lo, int row, int k,
                                         float a, float b) {
    __nv_bfloat16 h0 = __float2bfloat16(a), h1 = __float2bfloat16(b);
    __nv_bfloat16 l0 = __float2bfloat16(a - __bfloat162float(h0));
    __nv_bfloat16 l1 = __float2bfloat16(b - __bfloat162float(h1));
    uint32_t hw = (uint32_t)__bfloat16_as_ushort(h0)
                | ((uint32_t)__bfloat16_as_ushort(h1) << 16);
    uint32_t lw = (uint32_t)__bfloat16_as_ushort(l0)
                | ((uint32_t)__bfloat16_as_ushort(l1) << 16);
    uint32_t off = (uint32_t)(row * AS_STRIDE + k) * 2;
    *(uint32_t*)(hi + off) = hw;
    *(uint32_t*)(lo + off) = lw;
}

__device__ __forceinline__ void load_a_split(const float* src, int nrows,
                                             int relu, char* hi, char* lo,
                                             int tid) {
#pragma unroll
    for (int t = 0; t < 16; t++) {
        int idx = tid + t * 256;         // 4096 float4 total
        int row = idx >> 5;
        int k4  = (idx & 31) << 2;
        float4 v = make_float4(0.f, 0.f, 0.f, 0.f);
        if (row < nrows) v = *(const float4*)(src + (size_t)row * CC + k4);
        if (relu) {
            v.x = fmaxf(v.x, 0.f); v.y = fmaxf(v.y, 0.f);
            v.z = fmaxf(v.z, 0.f); v.w = fmaxf(v.w, 0.f);
        }
        cvt_pair(hi, lo, row, k4,     v.x, v.y);
        cvt_pair(hi, lo, row, k4 + 2, v.z, v.w);
    }
}

// copy pre-split bf16 W tile [128][128] row-major -> smem stride AS_STRIDE
__device__ __forceinline__ void copy_w_tile(const __nv_bfloat16* src, char* dst,
                                            int tid) {
#pragma unroll
    for (int t = 0; t < 8; t++) {
        int idx = tid + t * 256;         // 2048 uint4 (8 bf16 each)
        int row = idx >> 4;
        int k8  = (idx & 15) << 3;
        uint4 v = *(const uint4*)(src + row * CC + k8);
        *(uint4*)(dst + (uint32_t)(row * AS_STRIDE + k8) * 2) = v;
    }
}

__global__ __launch_bounds__(256, 1) void gemm3_tc_kernel(
    const float* __restrict__ x,
    const __nv_bfloat16* __restrict__ Wh, const __nv_bfloat16* __restrict__ Wl,
    int mat0,
    const float* __restrict__ b0, float* __restrict__ o0,
    const float* __restrict__ b1, float* __restrict__ o1,
    const float* __restrict__ b2, float* __restrict__ o2,
    int relu_in)
{
    extern __shared__ char sm[];
    const int tid  = threadIdx.x;
    const int wid  = tid >> 5;
    const int lane = tid & 31;
    const int g    = lane >> 2;          // 0..7
    const int tg   = lane & 3;           // 0..3
    const int row0 = blockIdx.x * 128;
    const int nrows = (NN - row0 < 128) ? (NN - row0) : 128;
    const int wm0 = (wid >> 2) * 64;     // warp tile m origin (0 / 64)
    const int wn0 = (wid & 3) * 32;      // warp tile n origin (0/32/64/96)

    // A tile -> bf16 hi/lo (once)
    load_a_split(x + (size_t)row0 * CC, nrows, relu_in,
                 sm + SM_AHI, sm + SM_ALO, tid);

    const float* bs[3] = {b0, b1, b2};
    float*       os[3] = {o0, o1, o2};

    // ldmatrix per-lane base addresses (u32 shared space)
    const uint32_t smb = (uint32_t)__cvta_generic_to_shared(sm);
    // A x4: lanes 0-7 rows m+0..7 @k, 8-15 rows m+8..15 @k, 16-23 rows m..7 @k+8,
    //       24-31 rows m+8..15 @k+8  -> row = lane&15, koff = (lane>>4)*8
    const uint32_t a_lane_off =
        (uint32_t)(((wm0 + (lane & 15)) * AS_STRIDE + ((lane >> 4) << 3)) * 2);
    const uint32_t ahi_base = smb + SM_AHI + a_lane_off;
    const uint32_t alo_base = smb + SM_ALO + a_lane_off;
    // B x4 (two n8 tiles): lanes 0-7 rows n0..7 @k, 8-15 rows n0..7 @k+8,
    //       16-23 rows n0+8..15 @k, 24-31 rows n0+8..15 @k+8
    const int b_row = (lane & 7) + ((lane & 16) ? 8 : 0);
    const uint32_t b_lane_off =
        (uint32_t)(((wn0 + b_row) * AS_STRIDE + ((lane & 8) ? 8 : 0)) * 2);
    const uint32_t bhi_base = smb + SM_BHI + b_lane_off;
    const uint32_t blo_base = smb + SM_BLO + b_lane_off;

    for (int j = 0; j < 3; j++) {
        __syncthreads();                 // previous Bs fully consumed
        copy_w_tile(Wh + (size_t)(mat0 + j) * CC * CC, sm + SM_BHI, tid);
        copy_w_tile(Wl + (size_t)(mat0 + j) * CC * CC, sm + SM_BLO, tid);
        __syncthreads();

        float acc[4][4][4];
#pragma unroll
        for (int ma = 0; ma < 4; ma++)
#pragma unroll
            for (int na = 0; na < 4; na++)
#pragma unroll
                for (int q = 0; q < 4; q++) acc[ma][na][q] = 0.f;

#pragma unroll
        for (int ks = 0; ks < 8; ks++) {
            const uint32_t kso = (uint32_t)(ks * 16 * 2);
            uint32_t bh[4][2], bl[4][2], af[4][4];
            // B fragments: 2x LDSM.x4 each for hi and lo (na pairs {0,1},{2,3})
#pragma unroll
            for (int nap = 0; nap < 2; nap++) {
                uint32_t r[4];
                ldsm_x4(r, bhi_base + (uint32_t)(nap * 16 * AS_STRIDE * 2) + kso);
                bh[nap * 2][0] = r[0]; bh[nap * 2][1] = r[1];
                bh[nap * 2 + 1][0] = r[2]; bh[nap * 2 + 1][1] = r[3];
                ldsm_x4(r, blo_base + (uint32_t)(nap * 16 * AS_STRIDE * 2) + kso);
                bl[nap * 2][0] = r[0]; bl[nap * 2][1] = r[1];
                bl[nap * 2 + 1][0] = r[2]; bl[nap * 2 + 1][1] = r[3];
            }
            // A_hi fragments: 4x LDSM.x4
#pragma unroll
            for (int ma = 0; ma < 4; ma++)
                ldsm_x4(af[ma], ahi_base + (uint32_t)(ma * 16 * AS_STRIDE * 2) + kso);
#pragma unroll
            for (int ma = 0; ma < 4; ma++)
#pragma unroll
                for (int na = 0; na < 4; na++)
                    mma16816(acc[ma][na], af[ma], bh[na]);
#pragma unroll
            for (int ma = 0; ma < 4; ma++)
#pragma unroll
                for (int na = 0; na < 4; na++)
                    mma16816(acc[ma][na], af[ma], bl[na]);
            // A_lo fragments (reuse af regs)
#pragma unroll
            for (int ma = 0; ma < 4; ma++)
                ldsm_x4(af[ma], alo_base + (uint32_t)(ma * 16 * AS_STRIDE * 2) + kso);
#pragma unroll
            for (int ma = 0; ma < 4; ma++)
#pragma unroll
                for (int na = 0; na < 4; na++)
                    mma16816(acc[ma][na], af[ma], bh[na]);
        }

        // epilogue: bias + direct gmem stores (float2 per atom-half)
        const float* bias = bs[j];
        float* o = os[j];
#pragma unroll
        for (int na = 0; na < 4; na++) {
            int col = wn0 + na * 8 + tg * 2;
            float2 bb = *(const float2*)(bias + col);
#pragma unroll
            for (int ma = 0; ma < 4; ma++) {
                int ra = row0 + wm0 + ma * 16 + g;
                if (ra < NN) {
                    float2 v = make_float2(acc[ma][na][0] + bb.x,
                                           acc[ma][na][1] + bb.y);
                    *(float2*)(o + (size_t)ra * CC + col) = v;
                }
                int rb = ra + 8;
                if (rb < NN) {
                    float2 v = make_float2(acc[ma][na][2] + bb.x,
                                           acc[ma][na][3] + bb.y);
                    *(float2*)(o + (size_t)rb * CC + col) = v;
                }
            }
        }
    }
}

// ---------------- fused attention + aggregation (warp per dst, no atomics) ---
__device__ __forceinline__ float leaky_dot(float4 a, float4 r, float4 t) {
    float4 m;
    m.x = a.x + r.x; m.x = m.x > 0.f ? m.x : NEG_SLOPE * m.x;
    m.y = a.y + r.y; m.y = m.y > 0.f ? m.y : NEG_SLOPE * m.y;
    m.z = a.z + r.z; m.z = m.z > 0.f ? m.z : NEG_SLOPE * m.z;
    m.w = a.w + r.w; m.w = m.w > 0.f ? m.w : NEG_SLOPE * m.w;
    float p = m.x * t.x;
    p = fmaf(m.y, t.y, p);
    p = fmaf(m.z, t.z, p);
    p = fmaf(m.w, t.w, p);
    return p;
}

__global__ __launch_bounds__(256) void aggr_kernel(
    const float* __restrict__ xl, const float* __restrict__ xr,
    const float* __restrict__ att, float* __restrict__ res_out)
{
    int gw   = (int)((blockIdx.x * 256u + threadIdx.x) >> 5);
    int lane = threadIdx.x & 31;
    if (gw >= NN) return;
    const int d = gw;

    float4 t = *(const float4*)(att + lane * 4);
    float4 r = *(const float4*)(xr + (size_t)d * CC + lane * 4);

    const int start = g_off[d];
    const int deg   = g_deg[d];          // >= 1 (self loop)

    float denom = 0.f;
    float4 acc = make_float4(0.f, 0.f, 0.f, 0.f);

    int jj = 0;
    for (; jj + 1 < deg; jj += 2) {
        int s0 = g_csr[start + jj];
        int s1 = g_csr[start + jj + 1];
        float4 a0 = *(const float4*)(xl + (size_t)s0 * CC + lane * 4);
        float4 a1 = *(const float4*)(xl + (size_t)s1 * CC + lane * 4);
        float p0 = leaky_dot(a0, r, t);
        float p1 = leaky_dot(a1, r, t);
#pragma unroll
        for (int off = 16; off > 0; off >>= 1) {
            p0 += __shfl_xor_sync(0xffffffffu, p0, off);
            p1 += __shfl_xor_sync(0xffffffffu, p1, off);
        }
        float ev0 = expf(p0);
        float ev1 = expf(p1);
        denom += ev0 + ev1;
        acc.x = fmaf(ev0, a0.x, fmaf(ev1, a1.x, acc.x));
        acc.y = fmaf(ev0, a0.y, fmaf(ev1, a1.y, acc.y));
        acc.z = fmaf(ev0, a0.z, fmaf(ev1, a1.z, acc.z));
        acc.w = fmaf(ev0, a0.w, fmaf(ev1, a1.w, acc.w));
    }
    if (jj < deg) {
        int s0 = g_csr[start + jj];
        float4 a0 = *(const float4*)(xl + (size_t)s0 * CC + lane * 4);
        float p0 = leaky_dot(a0, r, t);
#pragma unroll
        for (int off = 16; off > 0; off >>= 1)
            p0 += __shfl_xor_sync(0xffffffffu, p0, off);
        float ev0 = expf(p0);
        denom += ev0;
        acc.x = fmaf(ev0, a0.x, acc.x);
        acc.y = fmaf(ev0, a0.y, acc.y);
        acc.z = fmaf(ev0, a0.z, acc.z);
        acc.w = fmaf(ev0, a0.w, acc.w);
    }

    float inv = 1.f / denom;
    float* op = res_out + (size_t)d * CC + lane * 4;
    float4 rr = *(const float4*)op;
    float4 o = make_float4(fmaf(acc.x, inv, rr.x), fmaf(acc.y, inv, rr.y),
                           fmaf(acc.z, inv, rr.z), fmaf(acc.w, inv, rr.w));
    *(float4*)op = o;
}

// ---------------- launch ------------------------------------------------------
extern "C" void kernel_launch(void* const* d_in, const int* in_sizes, int n_in,
                              void* d_out, int out_size)
{
    const int*   ei    = (const int*)  d_in[0];
    const float* emb   = (const float*)d_in[1];
    const float* Wl1   = (const float*)d_in[2];
    const float* bl1   = (const float*)d_in[3];
    const float* Wr1   = (const float*)d_in[4];
    const float* br1   = (const float*)d_in[5];
    const float* att1  = (const float*)d_in[6];
    const float* Wres1 = (const float*)d_in[7];
    const float* bias1 = (const float*)d_in[8];
    const float* Wl2   = (const float*)d_in[9];
    const float* bl2   = (const float*)d_in[10];
    const float* Wr2   = (const float*)d_in[11];
    const float* br2   = (const float*)d_in[12];
    const float* att2  = (const float*)d_in[13];
    const float* Wres2 = (const float*)d_in[14];
    const float* bias2 = (const float*)d_in[15];
    float* out = (float*)d_out;

    float *xl, *xr, *h;
    __nv_bfloat16 *Wh, *Wl;
    int *deg, *cur;
    cudaGetSymbolAddress((void**)&xl,  g_xl);
    cudaGetSymbolAddress((void**)&xr,  g_xr);
    cudaGetSymbolAddress((void**)&h,   g_h);
    cudaGetSymbolAddress((void**)&Wh,  g_Wh);
    cudaGetSymbolAddress((void**)&Wl,  g_Wl);
    cudaGetSymbolAddress((void**)&deg, g_deg);
    cudaGetSymbolAddress((void**)&cur, g_cur);

    cudaFuncSetAttribute(gemm3_tc_kernel,
                         cudaFuncAttributeMaxDynamicSharedMemorySize, SM_TOTAL);

    const int edge_grid = (EP + 255) / 256;        // 2891
    const int gemm_grid = (NN + 127) / 128;        // 782
    const int aggr_grid = (NN * 32 + 255) / 256;   // 12500

    // Launch order chosen so ncu (-s 5 -c 1, memsets count) captures gemm3_tc.
    cudaMemsetAsync(deg, 0, NN * sizeof(int));                      // 0
    cudaMemsetAsync(cur, 0, NN * sizeof(int));                      // 1
    wsplit_kernel<<<(6 * CC * CC + 255) / 256, 256>>>(              // 2
        Wl1, Wr1, Wres1, Wl2, Wr2, Wres2);
    hist_kernel<<<edge_grid, 256>>>(ei);                            // 3
    scan1_kernel<<<NBLK, SCAN_BLK>>>();                             // 4
    gemm3_tc_kernel<<<gemm_grid, 256, SM_TOTAL>>>(                  // 5  <- profiled
        emb, Wh, Wl, 0, bl1, xl, br1, xr, bias1, h, 0);
    scan2_kernel<<<1, 128>>>();                                     // 6
    scan3_kernel<<<(NN + 255) / 256, 256>>>();                      // 7
    scatter_kernel<<<edge_grid, 256>>>(ei);                         // 8
    aggr_kernel<<<aggr_grid, 256>>>(xl, xr, att1, h);               // 9
    gemm3_tc_kernel<<<gemm_grid, 256, SM_TOTAL>>>(                  // 10
        h, Wh, Wl, 3, bl2, xl, br2, xr, bias2, out, 1);
    aggr_kernel<<<aggr_grid, 256>>>(xl, xr, att2, out);             // 11
}

// round 11
// speedup vs baseline: 1.4605x; 1.0453x over previous
#include <cuda_runtime.h>
#include <cuda_bf16.h>
#include <cstdint>

#define NN 100000
#define EE 640000
#define EP 740000            /* EE + NN self loops */
#define CC 128
#define NEG_SLOPE 0.2f
#define SCAN_BLK 1024
#define NBLK ((NN + SCAN_BLK - 1) / SCAN_BLK)   /* 98 */

// ---------------- device scratch ---------------------------------------------
__device__ __align__(16) float g_xl[(size_t)NN * CC];
__device__ __align__(16) float g_xr[(size_t)NN * CC];
__device__ __align__(16) float g_h [(size_t)NN * CC];
__device__ __align__(16) __nv_bfloat16 g_Wh[6 * CC * CC];  // weights hi (bf16)
__device__ __align__(16) __nv_bfloat16 g_Wl[6 * CC * CC];  // weights lo (bf16)
__device__ int   g_deg[NN];
__device__ int   g_cur[NN];
__device__ int   g_off[NN];
__device__ int   g_bsum[NBLK];
__device__ int   g_csr[EP];

// ---------------- weight pre-split (fp32 -> bf16 hi/lo) -----------------------
__global__ void wsplit_kernel(const float* __restrict__ W0, const float* __restrict__ W1,
                              const float* __restrict__ W2, const float* __restrict__ W3,
                              const float* __restrict__ W4, const float* __restrict__ W5)
{
    const float* Ws[6] = {W0, W1, W2, W3, W4, W5};
    int i = blockIdx.x * blockDim.x + threadIdx.x;
    if (i >= 6 * CC * CC) return;
    float v = Ws[i >> 14][i & 16383];
    __nv_bfloat16 h = __float2bfloat16(v);
    __nv_bfloat16 l = __float2bfloat16(v - __bfloat162float(h));
    g_Wh[i] = h;
    g_Wl[i] = l;
}

// ---------------- CSR build ---------------------------------------------------
__global__ void hist_kernel(const int* __restrict__ ei) {
    int e = blockIdx.x * blockDim.x + threadIdx.x;
    if (e >= EP) return;
    int d = (e < EE) ? ei[EE + e] : (e - EE);
    atomicAdd(&g_deg[d], 1);
}

__global__ void scan1_kernel() {
    __shared__ int sh[SCAN_BLK];
    int i = blockIdx.x * SCAN_BLK + threadIdx.x;
    int v = (i < NN) ? g_deg[i] : 0;
    sh[threadIdx.x] = v;
    __syncthreads();
    for (int o = 1; o < SCAN_BLK; o <<= 1) {
        int t = (threadIdx.x >= o) ? sh[threadIdx.x - o] : 0;
        __syncthreads();
        sh[threadIdx.x] += t;
        __syncthreads();
    }
    if (i < NN) g_off[i] = sh[threadIdx.x] - v;
    if (threadIdx.x == SCAN_BLK - 1) g_bsum[blockIdx.x] = sh[threadIdx.x];
}

__global__ void scan2_kernel() {
    __shared__ int sh[128];
    int b = threadIdx.x;
    int v = (b < NBLK) ? g_bsum[b] : 0;
    sh[b] = v;
    __syncthreads();
    for (int o = 1; o < 128; o <<= 1) {
        int t = (b >= o) ? sh[b - o] : 0;
        __syncthreads();
        sh[b] += t;
        __syncthreads();
    }
    if (b < NBLK) g_bsum[b] = sh[b] - v;
}

__global__ void scan3_kernel() {
    int i = blockIdx.x * blockDim.x + threadIdx.x;
    if (i < NN) g_off[i] += g_bsum[i / SCAN_BLK];
}

__global__ void scatter_kernel(const int* __restrict__ ei) {
    int e = blockIdx.x * blockDim.x + threadIdx.x;
    if (e >= EP) return;
    int s, d;
    if (e < EE) { s = ei[e]; d = ei[EE + e]; }
    else        { s = d = e - EE; }
    int pos = g_off[d] + atomicAdd(&g_cur[d], 1);
    g_csr[pos] = s;
}

// ================= HMMA (mma.sync) 3-output GEMM ==============================
// CTA tile stays 128x128 (R9: shrinking M doubled B traffic -> regression).
// R10: LDSM cut instr 4x, no change -> stall-bound, not issue-bound. Fix the
// stalls: 512 thr / 16 warps (4x4 grid of 32x32 warp tiles, occ 25%) and
// cp.async double-buffered B tiles (gmem latency of W(j+1) hidden behind
// mainloop j). fp32 split hi+lo bf16; D = Ah*Bh + Ah*Bl + Al*Bh.
#define AS_STRIDE 136                    /* bf16 units; LDSM rows 272B apart -> conflict-free */
#define TILE_B (128 * AS_STRIDE * 2)     /* 34816 bytes */
#define SM_AHI 0
#define SM_ALO (TILE_B)
#define SM_BB  (2 * TILE_B)              /* B buffers: buf*(2*TILE_B) + {0:hi, TILE_B:lo} */
#define SM_TOTAL (6 * TILE_B)            /* 208896 = 204 KB */

__device__ __forceinline__ void mma16816(float* c, const uint32_t* a,
                                         const uint32_t* b) {
    asm volatile(
        "mma.sync.aligned.m16n8k16.row.col.f32.bf16.bf16.f32 "
        "{%0,%1,%2,%3}, {%4,%5,%6,%7}, {%8,%9}, {%0,%1,%2,%3};"
        : "+f"(c[0]), "+f"(c[1]), "+f"(c[2]), "+f"(c[3])
        : "r"(a[0]), "r"(a[1]), "r"(a[2]), "r"(a[3]), "r"(b[0]), "r"(b[1]));
}

__device__ __forceinline__ void ldsm_x4(uint32_t* r, uint32_t addr) {
    asm volatile("ldmatrix.sync.aligned.m8n8.x4.shared.b16 {%0,%1,%2,%3}, [%4];"
                 : "=r"(r[0]), "=r"(r[1]), "=r"(r[2]), "=r"(r[3]) : "r"(addr));
}

__device__ __forceinline__ void cp_async16(uint32_t dst, const void* src) {
    asm volatile("cp.async.cg.shared.global [%0], [%1], 16;"
                 :: "r"(dst), "l"(src));
}
#define CP_COMMIT() asm volatile("cp.async.commit_group;" ::: "memory")
#define CP_WAIT1()  asm volatile("cp.async.wait_group 1;" ::: "memory")
#define CP_WAIT0()  asm volatile("cp.async.wait_group 0;" ::: "memory")

__device__ __forceinline__ void cvt_pair(char* hi, char* lo, int row, int k,
                                         float a, float b) {
    __nv_bfloat16 h0 = __float2bfloat16(a), h1 = __float2bfloat16(b);
    __nv_bfloat16 l0 = __float2bfloat16(a - __bfloat162float(h0));
    __nv_bfloat16 l1 = __float2bfloat16(b - __bfloat162float(h1));
    uint32_t hw = (uint32_t)__bfloat16_as_ushort(h0)
                | ((uint32_t)__bfloat16_as_ushort(h1) << 16);
    uint32_t lw = (uint32_t)__bfloat16_as_ushort(l0)
                | ((uint32_t)__bfloat16_as_ushort(l1) << 16);
    uint32_t off = (uint32_t)(row * AS_STRIDE + k) * 2;
    *(uint32_t*)(hi + off) = hw;
    *(uint32_t*)(lo + off) = lw;
}

// prefetch one pre-split W tile (hi+lo) into a B buffer via cp.async
__device__ __forceinline__ void prefetch_w(const __nv_bfloat16* srch,
                                           const __nv_bfloat16* srcl,
                                           uint32_t dsth, uint32_t dstl, int tid) {
#pragma unroll
    for (int t = 0; t < 4; t++) {
        int idx = tid + t * 512;         // 2048 x 16B per tile
        int row = idx >> 4;
        int k8  = (idx & 15) << 3;
        uint32_t off = (uint32_t)(row * AS_STRIDE + k8) * 2;
        cp_async16(dsth + off, srch + row * CC + k8);
        cp_async16(dstl + off, srcl + row * CC + k8);
    }
}

__global__ __launch_bounds__(512, 1) void gemm3_tc_kernel(
    const float* __restrict__ x,
    const __nv_bfloat16* __restrict__ Wh, const __nv_bfloat16* __restrict__ Wl,
    int mat0,
    const float* __restrict__ b0, float* __restrict__ o0,
    const float* __restrict__ b1, float* __restrict__ o1,
    const float* __restrict__ b2, float* __restrict__ o2,
    int relu_in)
{
    extern __shared__ char sm[];
    const int tid  = threadIdx.x;
    const int wid  = tid >> 5;
    const int lane = tid & 31;
    const int g    = lane >> 2;          // 0..7
    const int tg   = lane & 3;           // 0..3
    const int row0 = blockIdx.x * 128;
    const int nrows = (NN - row0 < 128) ? (NN - row0) : 128;
    const int wm0 = (wid >> 2) * 32;     // warp tile m origin (0/32/64/96)
    const int wn0 = (wid & 3) * 32;      // warp tile n origin (0/32/64/96)

    const uint32_t smb = (uint32_t)__cvta_generic_to_shared(sm);

    // prefetch B(0) immediately (overlaps with A conversion below)
    prefetch_w(Wh + (size_t)mat0 * CC * CC, Wl + (size_t)mat0 * CC * CC,
               smb + SM_BB, smb + SM_BB + TILE_B, tid);
    CP_COMMIT();

    // A tile -> bf16 hi/lo (once); 4096 float4 over 512 threads
#pragma unroll
    for (int t = 0; t < 8; t++) {
        int idx = tid + t * 512;
        int row = idx >> 5;
        int k4  = (idx & 31) << 2;
        float4 v = make_float4(0.f, 0.f, 0.f, 0.f);
        if (row < nrows)
            v = *(const float4*)(x + (size_t)(row0 + row) * CC + k4);
        if (relu_in) {
            v.x = fmaxf(v.x, 0.f); v.y = fmaxf(v.y, 0.f);
            v.z = fmaxf(v.z, 0.f); v.w = fmaxf(v.w, 0.f);
        }
        cvt_pair(sm + SM_AHI, sm + SM_ALO, row, k4,     v.x, v.y);
        cvt_pair(sm + SM_AHI, sm + SM_ALO, row, k4 + 2, v.z, v.w);
    }

    const float* bs[3] = {b0, b1, b2};
    float*       os[3] = {o0, o1, o2};

    // ldmatrix per-lane base addresses
    const uint32_t a_lane_off =
        (uint32_t)(((wm0 + (lane & 15)) * AS_STRIDE + ((lane >> 4) << 3)) * 2);
    const uint32_t ahi_base = smb + SM_AHI + a_lane_off;
    const uint32_t alo_base = smb + SM_ALO + a_lane_off;
    const int b_row = (lane & 7) + ((lane & 16) ? 8 : 0);
    const uint32_t b_lane_off =
        (uint32_t)(((wn0 + b_row) * AS_STRIDE + ((lane & 8) ? 8 : 0)) * 2);

    for (int j = 0; j < 3; j++) {
        if (j + 1 < 3) {                 // prefetch B(j+1) into alternate buffer
            uint32_t bb = smb + SM_BB + (uint32_t)(((j + 1) & 1) * 2 * TILE_B);
            prefetch_w(Wh + (size_t)(mat0 + j + 1) * CC * CC,
                       Wl + (size_t)(mat0 + j + 1) * CC * CC,
                       bb, bb + TILE_B, tid);
            CP_COMMIT();
            CP_WAIT1();                  // B(j) complete (one newer group pending)
        } else {
            CP_WAIT0();
        }
        __syncthreads();                 // B(j) visible; A visible (j==0)

        const uint32_t bbase = smb + SM_BB + (uint32_t)((j & 1) * 2 * TILE_B);
        const uint32_t bhi_base = bbase + b_lane_off;
        const uint32_t blo_base = bbase + TILE_B + b_lane_off;

        float acc[2][4][4];
#pragma unroll
        for (int ma = 0; ma < 2; ma++)
#pragma unroll
            for (int na = 0; na < 4; na++)
#pragma unroll
                for (int q = 0; q < 4; q++) acc[ma][na][q] = 0.f;

#pragma unroll
        for (int ks = 0; ks < 8; ks++) {
            const uint32_t kso = (uint32_t)(ks * 16 * 2);
            uint32_t bh[4][2], bl[4][2], af[2][4];
#pragma unroll
            for (int nap = 0; nap < 2; nap++) {
                uint32_t r[4];
                ldsm_x4(r, bhi_base + (uint32_t)(nap * 16 * AS_STRIDE * 2) + kso);
                bh[nap * 2][0] = r[0]; bh[nap * 2][1] = r[1];
                bh[nap * 2 + 1][0] = r[2]; bh[nap * 2 + 1][1] = r[3];
                ldsm_x4(r, blo_base + (uint32_t)(nap * 16 * AS_STRIDE * 2) + kso);
                bl[nap * 2][0] = r[0]; bl[nap * 2][1] = r[1];
                bl[nap * 2 + 1][0] = r[2]; bl[nap * 2 + 1][1] = r[3];
            }
#pragma unroll
            for (int ma = 0; ma < 2; ma++)
                ldsm_x4(af[ma], ahi_base + (uint32_t)(ma * 16 * AS_STRIDE * 2) + kso);
#pragma unroll
            for (int ma = 0; ma < 2; ma++)
#pragma unroll
                for (int na = 0; na < 4; na++)
                    mma16816(acc[ma][na], af[ma], bh[na]);
#pragma unroll
            for (int ma = 0; ma < 2; ma++)
#pragma unroll
                for (int na = 0; na < 4; na++)
                    mma16816(acc[ma][na], af[ma], bl[na]);
#pragma unroll
            for (int ma = 0; ma < 2; ma++)
                ldsm_x4(af[ma], alo_base + (uint32_t)(ma * 16 * AS_STRIDE * 2) + kso);
#pragma unroll
            for (int ma = 0; ma < 2; ma++)
#pragma unroll
                for (int na = 0; na < 4; na++)
                    mma16816(acc[ma][na], af[ma], bh[na]);
        }

        // epilogue: bias + direct gmem stores (float2 per atom-half)
        const float* bias = bs[j];
        float* o = os[j];
#pragma unroll
        for (int na = 0; na < 4; na++) {
            int col = wn0 + na * 8 + tg * 2;
            float2 bb2 = *(const float2*)(bias + col);
#pragma unroll
            for (int ma = 0; ma < 2; ma++) {
                int ra = row0 + wm0 + ma * 16 + g;
                if (ra < NN) {
                    float2 v = make_float2(acc[ma][na][0] + bb2.x,
                                           acc[ma][na][1] + bb2.y);
                    *(float2*)(o + (size_t)ra * CC + col) = v;
                }
                int rb = ra + 8;
                if (rb < NN) {
                    float2 v = make_float2(acc[ma][na][2] + bb2.x,
                                           acc[ma][na][3] + bb2.y);
                    *(float2*)(o + (size_t)rb * CC + col) = v;
                }
            }
        }
        __syncthreads();                 // buf (j&1) consumed before j+2 prefetch
    }
}

// ---------------- fused attention + aggregation (warp per dst, no atomics) ---
__device__ __forceinline__ float leaky_dot(float4 a, float4 r, float4 t) {
    float4 m;
    m.x = a.x + r.x; m.x = m.x > 0.f ? m.x : NEG_SLOPE * m.x;
    m.y = a.y + r.y; m.y = m.y > 0.f ? m.y : NEG_SLOPE * m.y;
    m.z = a.z + r.z; m.z = m.z > 0.f ? m.z : NEG_SLOPE * m.z;
    m.w = a.w + r.w; m.w = m.w > 0.f ? m.w : NEG_SLOPE * m.w;
    float p = m.x * t.x;
    p = fmaf(m.y, t.y, p);
    p = fmaf(m.z, t.z, p);
    p = fmaf(m.w, t.w, p);
    return p;
}

__global__ __launch_bounds__(256) void aggr_kernel(
    const float* __restrict__ xl, const float* __restrict__ xr,
    const float* __restrict__ att, float* __restrict__ res_out)
{
    int gw   = (int)((blockIdx.x * 256u + threadIdx.x) >> 5);
    int lane = threadIdx.x & 31;
    if (gw >= NN) return;
    const int d = gw;

    float4 t = *(const float4*)(att + lane * 4);
    float4 r = *(const float4*)(xr + (size_t)d * CC + lane * 4);

    const int start = g_off[d];
    const int deg   = g_deg[d];          // >= 1 (self loop)

    float denom = 0.f;
    float4 acc = make_float4(0.f, 0.f, 0.f, 0.f);

    int jj = 0;
    for (; jj + 1 < deg; jj += 2) {
        int s0 = g_csr[start + jj];
        int s1 = g_csr[start + jj + 1];
        float4 a0 = *(const float4*)(xl + (size_t)s0 * CC + lane * 4);
        float4 a1 = *(const float4*)(xl + (size_t)s1 * CC + lane * 4);
        float p0 = leaky_dot(a0, r, t);
        float p1 = leaky_dot(a1, r, t);
#pragma unroll
        for (int off = 16; off > 0; off >>= 1) {
            p0 += __shfl_xor_sync(0xffffffffu, p0, off);
            p1 += __shfl_xor_sync(0xffffffffu, p1, off);
        }
        float ev0 = expf(p0);
        float ev1 = expf(p1);
        denom += ev0 + ev1;
        acc.x = fmaf(ev0, a0.x, fmaf(ev1, a1.x, acc.x));
        acc.y = fmaf(ev0, a0.y, fmaf(ev1, a1.y, acc.y));
        acc.z = fmaf(ev0, a0.z, fmaf(ev1, a1.z, acc.z));
        acc.w = fmaf(ev0, a0.w, fmaf(ev1, a1.w, acc.w));
    }
    if (jj < deg) {
        int s0 = g_csr[start + jj];
        float4 a0 = *(const float4*)(xl + (size_t)s0 * CC + lane * 4);
        float p0 = leaky_dot(a0, r, t);
#pragma unroll
        for (int off = 16; off > 0; off >>= 1)
            p0 += __shfl_xor_sync(0xffffffffu, p0, off);
        float ev0 = expf(p0);
        denom += ev0;
        acc.x = fmaf(ev0, a0.x, acc.x);
        acc.y = fmaf(ev0, a0.y, acc.y);
        acc.z = fmaf(ev0, a0.z, acc.z);
        acc.w = fmaf(ev0, a0.w, acc.w);
    }

    float inv = 1.f / denom;
    float* op = res_out + (size_t)d * CC + lane * 4;
    float4 rr = *(const float4*)op;
    float4 o = make_float4(fmaf(acc.x, inv, rr.x), fmaf(acc.y, inv, rr.y),
                           fmaf(acc.z, inv, rr.z), fmaf(acc.w, inv, rr.w));
    *(float4*)op = o;
}

// ---------------- launch ------------------------------------------------------
extern "C" void kernel_launch(void* const* d_in, const int* in_sizes, int n_in,
                              void* d_out, int out_size)
{
    const int*   ei    = (const int*)  d_in[0];
    const float* emb   = (const float*)d_in[1];
    const float* Wl1   = (const float*)d_in[2];
    const float* bl1   = (const float*)d_in[3];
    const float* Wr1   = (const float*)d_in[4];
    const float* br1   = (const float*)d_in[5];
    const float* att1  = (const float*)d_in[6];
    const float* Wres1 = (const float*)d_in[7];
    const float* bias1 = (const float*)d_in[8];
    const float* Wl2   = (const float*)d_in[9];
    const float* bl2   = (const float*)d_in[10];
    const float* Wr2   = (const float*)d_in[11];
    const float* br2   = (const float*)d_in[12];
    const float* att2  = (const float*)d_in[13];
    const float* Wres2 = (const float*)d_in[14];
    const float* bias2 = (const float*)d_in[15];
    float* out = (float*)d_out;

    float *xl, *xr, *h;
    __nv_bfloat16 *Wh, *Wl;
    int *deg, *cur;
    cudaGetSymbolAddress((void**)&xl,  g_xl);
    cudaGetSymbolAddress((void**)&xr,  g_xr);
    cudaGetSymbolAddress((void**)&h,   g_h);
    cudaGetSymbolAddress((void**)&Wh,  g_Wh);
    cudaGetSymbolAddress((void**)&Wl,  g_Wl);
    cudaGetSymbolAddress((void**)&deg, g_deg);
    cudaGetSymbolAddress((void**)&cur, g_cur);

    cudaFuncSetAttribute(gemm3_tc_kernel,
                         cudaFuncAttributeMaxDynamicSharedMemorySize, SM_TOTAL);

    const int edge_grid = (EP + 255) / 256;        // 2891
    const int gemm_grid = (NN + 127) / 128;        // 782
    const int aggr_grid = (NN * 32 + 255) / 256;   // 12500

    // Launch order chosen so ncu (-s 5 -c 1, memsets count) captures gemm3_tc.
    cudaMemsetAsync(deg, 0, NN * sizeof(int));                      // 0
    cudaMemsetAsync(cur, 0, NN * sizeof(int));                      // 1
    wsplit_kernel<<<(6 * CC * CC + 255) / 256, 256>>>(              // 2
        Wl1, Wr1, Wres1, Wl2, Wr2, Wres2);
    hist_kernel<<<edge_grid, 256>>>(ei);                            // 3
    scan1_kernel<<<NBLK, SCAN_BLK>>>();                             // 4
    gemm3_tc_kernel<<<gemm_grid, 512, SM_TOTAL>>>(                  // 5  <- profiled
        emb, Wh, Wl, 0, bl1, xl, br1, xr, bias1, h, 0);
    scan2_kernel<<<1, 128>>>();                                     // 6
    scan3_kernel<<<(NN + 255) / 256, 256>>>();                      // 7
    scatter_kernel<<<edge_grid, 256>>>(ei);                         // 8
    aggr_kernel<<<aggr_grid, 256>>>(xl, xr, att1, h);               // 9
    gemm3_tc_kernel<<<gemm_grid, 512, SM_TOTAL>>>(                  // 10
        h, Wh, Wl, 3, bl2, xl, br2, xr, bias2, out, 1);
    aggr_kernel<<<aggr_grid, 256>>>(xl, xr, att2, out);             // 11
}

// round 12
// speedup vs baseline: 1.6212x; 1.1100x over previous
#include <cuda_runtime.h>
#include <cuda_fp16.h>
#include <cstdint>

#define NN 100000
#define EE 640000
#define EP 740000            /* EE + NN self loops */
#define CC 128
#define NEG_SLOPE 0.2f
#define SCAN_BLK 1024
#define NBLK ((NN + SCAN_BLK - 1) / SCAN_BLK)   /* 98 */

// ---------------- device scratch ---------------------------------------------
__device__ __align__(16) float g_xl[(size_t)NN * CC];
__device__ __align__(16) float g_xr[(size_t)NN * CC];
__device__ __align__(16) float g_h [(size_t)NN * CC];
__device__ __align__(16) __half g_Wh[6 * CC * CC];  // weights hi (fp16)
__device__ __align__(16) __half g_Wl[6 * CC * CC];  // weights lo (fp16)
__device__ int   g_deg[NN];
__device__ int   g_cur[NN];
__device__ int   g_off[NN];
__device__ int   g_bsum[NBLK];
__device__ int   g_csr[EP];

// ---------------- weight pre-split (fp32 -> fp16 hi/lo) -----------------------
__global__ void wsplit_kernel(const float* __restrict__ W0, const float* __restrict__ W1,
                              const float* __restrict__ W2, const float* __restrict__ W3,
                              const float* __restrict__ W4, const float* __restrict__ W5)
{
    const float* Ws[6] = {W0, W1, W2, W3, W4, W5};
    int i = blockIdx.x * blockDim.x + threadIdx.x;
    if (i >= 6 * CC * CC) return;
    float v = Ws[i >> 14][i & 16383];
    __half h = __float2half_rn(v);
    __half l = __float2half_rn(v - __half2float(h));
    g_Wh[i] = h;
    g_Wl[i] = l;
}

// ---------------- CSR build ---------------------------------------------------
__global__ void hist_kernel(const int* __restrict__ ei) {
    int e = blockIdx.x * blockDim.x + threadIdx.x;
    if (e >= EP) return;
    int d = (e < EE) ? ei[EE + e] : (e - EE);
    atomicAdd(&g_deg[d], 1);
}

__global__ void scan1_kernel() {
    __shared__ int sh[SCAN_BLK];
    int i = blockIdx.x * SCAN_BLK + threadIdx.x;
    int v = (i < NN) ? g_deg[i] : 0;
    sh[threadIdx.x] = v;
    __syncthreads();
    for (int o = 1; o < SCAN_BLK; o <<= 1) {
        int t = (threadIdx.x >= o) ? sh[threadIdx.x - o] : 0;
        __syncthreads();
        sh[threadIdx.x] += t;
        __syncthreads();
    }
    if (i < NN) g_off[i] = sh[threadIdx.x] - v;
    if (threadIdx.x == SCAN_BLK - 1) g_bsum[blockIdx.x] = sh[threadIdx.x];
}

__global__ void scan2_kernel() {
    __shared__ int sh[128];
    int b = threadIdx.x;
    int v = (b < NBLK) ? g_bsum[b] : 0;
    sh[b] = v;
    __syncthreads();
    for (int o = 1; o < 128; o <<= 1) {
        int t = (b >= o) ? sh[b - o] : 0;
        __syncthreads();
        sh[b] += t;
        __syncthreads();
    }
    if (b < NBLK) g_bsum[b] = sh[b] - v;
}

__global__ void scan3_kernel() {
    int i = blockIdx.x * blockDim.x + threadIdx.x;
    if (i < NN) g_off[i] += g_bsum[i / SCAN_BLK];
}

__global__ void scatter_kernel(const int* __restrict__ ei) {
    int e = blockIdx.x * blockDim.x + threadIdx.x;
    if (e >= EP) return;
    int s, d;
    if (e < EE) { s = ei[e]; d = ei[EE + e]; }
    else        { s = d = e - EE; }
    int pos = g_off[d] + atomicAdd(&g_cur[d], 1);
    g_csr[pos] = s;
}

// ================= HMMA (mma.sync) 3-output GEMM ==============================
// R8-R11 invariance (tensor pinned at 40-44% across occ/LDS/prefetch changes)
// => mma.sync path is throughput-saturated (~512 MAC/cyc/SM). Cut MMA work
// 3->2 terms: fp16 2-term split, D = Ah*Wh + Ah*Wl (A rounded to fp16; dropped
// term sigma ~2^-11/sqrt(3) ~ 2.8e-4/layer; R11's 6e-6 validated this model).
// 512 thr / 16 warps, 4x4 grid of 32x32 warp tiles; cp.async double-buffered W.
#define AS_STRIDE 136                    /* fp16 units; LDSM rows 272B apart -> conflict-free */
#define TILE_B (128 * AS_STRIDE * 2)     /* 34816 bytes */
#define SM_AH  0
#define SM_BB  (TILE_B)                  /* B buffers: buf*(2*TILE_B) + {0:hi, TILE_B:lo} */
#define SM_TOTAL (5 * TILE_B)            /* 174080 = 170 KB */

__device__ __forceinline__ void mma16816(float* c, const uint32_t* a,
                                         const uint32_t* b) {
    asm volatile(
        "mma.sync.aligned.m16n8k16.row.col.f32.f16.f16.f32 "
        "{%0,%1,%2,%3}, {%4,%5,%6,%7}, {%8,%9}, {%0,%1,%2,%3};"
        : "+f"(c[0]), "+f"(c[1]), "+f"(c[2]), "+f"(c[3])
        : "r"(a[0]), "r"(a[1]), "r"(a[2]), "r"(a[3]), "r"(b[0]), "r"(b[1]));
}

__device__ __forceinline__ void ldsm_x4(uint32_t* r, uint32_t addr) {
    asm volatile("ldmatrix.sync.aligned.m8n8.x4.shared.b16 {%0,%1,%2,%3}, [%4];"
                 : "=r"(r[0]), "=r"(r[1]), "=r"(r[2]), "=r"(r[3]) : "r"(addr));
}

__device__ __forceinline__ void cp_async16(uint32_t dst, const void* src) {
    asm volatile("cp.async.cg.shared.global [%0], [%1], 16;"
                 :: "r"(dst), "l"(src));
}
#define CP_COMMIT() asm volatile("cp.async.commit_group;" ::: "memory")
#define CP_WAIT1()  asm volatile("cp.async.wait_group 1;" ::: "memory")
#define CP_WAIT0()  asm volatile("cp.async.wait_group 0;" ::: "memory")

// prefetch one pre-split W tile (hi+lo) into a B buffer via cp.async
__device__ __forceinline__ void prefetch_w(const __half* srch, const __half* srcl,
                                           uint32_t dsth, uint32_t dstl, int tid) {
#pragma unroll
    for (int t = 0; t < 4; t++) {
        int idx = tid + t * 512;         // 2048 x 16B per tile
        int row = idx >> 4;
        int k8  = (idx & 15) << 3;
        uint32_t off = (uint32_t)(row * AS_STRIDE + k8) * 2;
        cp_async16(dsth + off, srch + row * CC + k8);
        cp_async16(dstl + off, srcl + row * CC + k8);
    }
}

__global__ __launch_bounds__(512, 1) void gemm3_tc_kernel(
    const float* __restrict__ x,
    const __half* __restrict__ Wh, const __half* __restrict__ Wl,
    int mat0,
    const float* __restrict__ b0, float* __restrict__ o0,
    const float* __restrict__ b1, float* __restrict__ o1,
    const float* __restrict__ b2, float* __restrict__ o2,
    int relu_in)
{
    extern __shared__ char sm[];
    const int tid  = threadIdx.x;
    const int wid  = tid >> 5;
    const int lane = tid & 31;
    const int g    = lane >> 2;          // 0..7
    const int tg   = lane & 3;           // 0..3
    const int row0 = blockIdx.x * 128;
    const int nrows = (NN - row0 < 128) ? (NN - row0) : 128;
    const int wm0 = (wid >> 2) * 32;     // warp tile m origin (0/32/64/96)
    const int wn0 = (wid & 3) * 32;      // warp tile n origin (0/32/64/96)

    const uint32_t smb = (uint32_t)__cvta_generic_to_shared(sm);

    // prefetch B(0) immediately (overlaps with A conversion below)
    prefetch_w(Wh + (size_t)mat0 * CC * CC, Wl + (size_t)mat0 * CC * CC,
               smb + SM_BB, smb + SM_BB + TILE_B, tid);
    CP_COMMIT();

    // A tile -> fp16 (rounded); 4096 float4 over 512 threads
#pragma unroll
    for (int t = 0; t < 8; t++) {
        int idx = tid + t * 512;
        int row = idx >> 5;
        int k4  = (idx & 31) << 2;
        float4 v = make_float4(0.f, 0.f, 0.f, 0.f);
        if (row < nrows)
            v = *(const float4*)(x + (size_t)(row0 + row) * CC + k4);
        if (relu_in) {
            v.x = fmaxf(v.x, 0.f); v.y = fmaxf(v.y, 0.f);
            v.z = fmaxf(v.z, 0.f); v.w = fmaxf(v.w, 0.f);
        }
        __half2 p0 = __floats2half2_rn(v.x, v.y);
        __half2 p1 = __floats2half2_rn(v.z, v.w);
        uint32_t off = (uint32_t)(row * AS_STRIDE + k4) * 2;
        *(__half2*)(sm + SM_AH + off)     = p0;
        *(__half2*)(sm + SM_AH + off + 4) = p1;
    }

    const float* bs[3] = {b0, b1, b2};
    float*       os[3] = {o0, o1, o2};

    // ldmatrix per-lane base addresses
    const uint32_t a_lane_off =
        (uint32_t)(((wm0 + (lane & 15)) * AS_STRIDE + ((lane >> 4) << 3)) * 2);
    const uint32_t ah_base = smb + SM_AH + a_lane_off;
    const int b_row = (lane & 7) + ((lane & 16) ? 8 : 0);
    const uint32_t b_lane_off =
        (uint32_t)(((wn0 + b_row) * AS_STRIDE + ((lane & 8) ? 8 : 0)) * 2);

    for (int j = 0; j < 3; j++) {
        if (j + 1 < 3) {                 // prefetch B(j+1) into alternate buffer
            uint32_t bb = smb + SM_BB + (uint32_t)(((j + 1) & 1) * 2 * TILE_B);
            prefetch_w(Wh + (size_t)(mat0 + j + 1) * CC * CC,
                       Wl + (size_t)(mat0 + j + 1) * CC * CC,
                       bb, bb + TILE_B, tid);
            CP_COMMIT();
            CP_WAIT1();                  // B(j) complete (one newer group pending)
        } else {
            CP_WAIT0();
        }
        __syncthreads();                 // B(j) visible; A visible (j==0)

        const uint32_t bbase = smb + SM_BB + (uint32_t)((j & 1) * 2 * TILE_B);
        const uint32_t bhi_base = bbase + b_lane_off;
        const uint32_t blo_base = bbase + TILE_B + b_lane_off;

        float acc[2][4][4];
#pragma unroll
        for (int ma = 0; ma < 2; ma++)
#pragma unroll
            for (int na = 0; na < 4; na++)
#pragma unroll
                for (int q = 0; q < 4; q++) acc[ma][na][q] = 0.f;

#pragma unroll
        for (int ks = 0; ks < 8; ks++) {
            const uint32_t kso = (uint32_t)(ks * 16 * 2);
            uint32_t bh[4][2], bl[4][2], af[2][4];
#pragma unroll
            for (int nap = 0; nap < 2; nap++) {
                uint32_t r[4];
                ldsm_x4(r, bhi_base + (uint32_t)(nap * 16 * AS_STRIDE * 2) + kso);
                bh[nap * 2][0] = r[0]; bh[nap * 2][1] = r[1];
                bh[nap * 2 + 1][0] = r[2]; bh[nap * 2 + 1][1] = r[3];
                ldsm_x4(r, blo_base + (uint32_t)(nap * 16 * AS_STRIDE * 2) + kso);
                bl[nap * 2][0] = r[0]; bl[nap * 2][1] = r[1];
                bl[nap * 2 + 1][0] = r[2]; bl[nap * 2 + 1][1] = r[3];
            }
#pragma unroll
            for (int ma = 0; ma < 2; ma++)
                ldsm_x4(af[ma], ah_base + (uint32_t)(ma * 16 * AS_STRIDE * 2) + kso);
#pragma unroll
            for (int ma = 0; ma < 2; ma++)
#pragma unroll
                for (int na = 0; na < 4; na++)
                    mma16816(acc[ma][na], af[ma], bh[na]);
#pragma unroll
            for (int ma = 0; ma < 2; ma++)
#pragma unroll
                for (int na = 0; na < 4; na++)
                    mma16816(acc[ma][na], af[ma], bl[na]);
        }

        // epilogue: bias + direct gmem stores (float2 per atom-half)
        const float* bias = bs[j];
        float* o = os[j];
#pragma unroll
        for (int na = 0; na < 4; na++) {
            int col = wn0 + na * 8 + tg * 2;
            float2 bb2 = *(const float2*)(bias + col);
#pragma unroll
            for (int ma = 0; ma < 2; ma++) {
                int ra = row0 + wm0 + ma * 16 + g;
                if (ra < NN) {
                    float2 v = make_float2(acc[ma][na][0] + bb2.x,
                                           acc[ma][na][1] + bb2.y);
                    *(float2*)(o + (size_t)ra * CC + col) = v;
                }
                int rb = ra + 8;
                if (rb < NN) {
                    float2 v = make_float2(acc[ma][na][2] + bb2.x,
                                           acc[ma][na][3] + bb2.y);
                    *(float2*)(o + (size_t)rb * CC + col) = v;
                }
            }
        }
        __syncthreads();                 // buf (j&1) consumed before j+2 prefetch
    }
}

// ---------------- fused attention + aggregation (warp per dst, no atomics) ---
__device__ __forceinline__ float leaky_dot(float4 a, float4 r, float4 t) {
    float4 m;
    m.x = a.x + r.x; m.x = m.x > 0.f ? m.x : NEG_SLOPE * m.x;
    m.y = a.y + r.y; m.y = m.y > 0.f ? m.y : NEG_SLOPE * m.y;
    m.z = a.z + r.z; m.z = m.z > 0.f ? m.z : NEG_SLOPE * m.z;
    m.w = a.w + r.w; m.w = m.w > 0.f ? m.w : NEG_SLOPE * m.w;
    float p = m.x * t.x;
    p = fmaf(m.y, t.y, p);
    p = fmaf(m.z, t.z, p);
    p = fmaf(m.w, t.w, p);
    return p;
}

__global__ __launch_bounds__(256) void aggr_kernel(
    const float* __restrict__ xl, const float* __restrict__ xr,
    const float* __restrict__ att, float* __restrict__ res_out)
{
    int gw   = (int)((blockIdx.x * 256u + threadIdx.x) >> 5);
    int lane = threadIdx.x & 31;
    if (gw >= NN) return;
    const int d = gw;

    float4 t = *(const float4*)(att + lane * 4);
    float4 r = *(const float4*)(xr + (size_t)d * CC + lane * 4);

    const int start = g_off[d];
    const int deg   = g_deg[d];          // >= 1 (self loop)

    float denom = 0.f;
    float4 acc = make_float4(0.f, 0.f, 0.f, 0.f);

    int jj = 0;
    for (; jj + 1 < deg; jj += 2) {
        int s0 = g_csr[start + jj];
        int s1 = g_csr[start + jj + 1];
        float4 a0 = *(const float4*)(xl + (size_t)s0 * CC + lane * 4);
        float4 a1 = *(const float4*)(xl + (size_t)s1 * CC + lane * 4);
        float p0 = leaky_dot(a0, r, t);
        float p1 = leaky_dot(a1, r, t);
#pragma unroll
        for (int off = 16; off > 0; off >>= 1) {
            p0 += __shfl_xor_sync(0xffffffffu, p0, off);
            p1 += __shfl_xor_sync(0xffffffffu, p1, off);
        }
        float ev0 = expf(p0);
        float ev1 = expf(p1);
        denom += ev0 + ev1;
        acc.x = fmaf(ev0, a0.x, fmaf(ev1, a1.x, acc.x));
        acc.y = fmaf(ev0, a0.y, fmaf(ev1, a1.y, acc.y));
        acc.z = fmaf(ev0, a0.z, fmaf(ev1, a1.z, acc.z));
        acc.w = fmaf(ev0, a0.w, fmaf(ev1, a1.w, acc.w));
    }
    if (jj < deg) {
        int s0 = g_csr[start + jj];
        float4 a0 = *(const float4*)(xl + (size_t)s0 * CC + lane * 4);
        float p0 = leaky_dot(a0, r, t);
#pragma unroll
        for (int off = 16; off > 0; off >>= 1)
            p0 += __shfl_xor_sync(0xffffffffu, p0, off);
        float ev0 = expf(p0);
        denom += ev0;
        acc.x = fmaf(ev0, a0.x, acc.x);
        acc.y = fmaf(ev0, a0.y, acc.y);
        acc.z = fmaf(ev0, a0.z, acc.z);
        acc.w = fmaf(ev0, a0.w, acc.w);
    }

    float inv = 1.f / denom;
    float* op = res_out + (size_t)d * CC + lane * 4;
    float4 rr = *(const float4*)op;
    float4 o = make_float4(fmaf(acc.x, inv, rr.x), fmaf(acc.y, inv, rr.y),
                           fmaf(acc.z, inv, rr.z), fmaf(acc.w, inv, rr.w));
    *(float4*)op = o;
}

// ---------------- launch ------------------------------------------------------
extern "C" void kernel_launch(void* const* d_in, const int* in_sizes, int n_in,
                              void* d_out, int out_size)
{
    const int*   ei    = (const int*)  d_in[0];
    const float* emb   = (const float*)d_in[1];
    const float* Wl1   = (const float*)d_in[2];
    const float* bl1   = (const float*)d_in[3];
    const float* Wr1   = (const float*)d_in[4];
    const float* br1   = (const float*)d_in[5];
    const float* att1  = (const float*)d_in[6];
    const float* Wres1 = (const float*)d_in[7];
    const float* bias1 = (const float*)d_in[8];
    const float* Wl2   = (const float*)d_in[9];
    const float* bl2   = (const float*)d_in[10];
    const float* Wr2   = (const float*)d_in[11];
    const float* br2   = (const float*)d_in[12];
    const float* att2  = (const float*)d_in[13];
    const float* Wres2 = (const float*)d_in[14];
    const float* bias2 = (const float*)d_in[15];
    float* out = (float*)d_out;

    float *xl, *xr, *h;
    __half *Wh, *Wl;
    int *deg, *cur;
    cudaGetSymbolAddress((void**)&xl,  g_xl);
    cudaGetSymbolAddress((void**)&xr,  g_xr);
    cudaGetSymbolAddress((void**)&h,   g_h);
    cudaGetSymbolAddress((void**)&Wh,  g_Wh);
    cudaGetSymbolAddress((void**)&Wl,  g_Wl);
    cudaGetSymbolAddress((void**)&deg, g_deg);
    cudaGetSymbolAddress((void**)&cur, g_cur);

    cudaFuncSetAttribute(gemm3_tc_kernel,
                         cudaFuncAttributeMaxDynamicSharedMemorySize, SM_TOTAL);

    const int edge_grid = (EP + 255) / 256;        // 2891
    const int gemm_grid = (NN + 127) / 128;        // 782
    const int aggr_grid = (NN * 32 + 255) / 256;   // 12500

    // Launch order chosen so ncu (-s 5 -c 1, memsets count) captures gemm3_tc.
    cudaMemsetAsync(deg, 0, NN * sizeof(int));                      // 0
    cudaMemsetAsync(cur, 0, NN * sizeof(int));                      // 1
    wsplit_kernel<<<(6 * CC * CC + 255) / 256, 256>>>(              // 2
        Wl1, Wr1, Wres1, Wl2, Wr2, Wres2);
    hist_kernel<<<edge_grid, 256>>>(ei);                            // 3
    scan1_kernel<<<NBLK, SCAN_BLK>>>();                             // 4
    gemm3_tc_kernel<<<gemm_grid, 512, SM_TOTAL>>>(                  // 5  <- profiled
        emb, Wh, Wl, 0, bl1, xl, br1, xr, bias1, h, 0);
    scan2_kernel<<<1, 128>>>();                                     // 6
    scan3_kernel<<<(NN + 255) / 256, 256>>>();                      // 7
    scatter_kernel<<<edge_grid, 256>>>(ei);                         // 8
    aggr_kernel<<<aggr_grid, 256>>>(xl, xr, att1, h);               // 9
    gemm3_tc_kernel<<<gemm_grid, 512, SM_TOTAL>>>(                  // 10
        h, Wh, Wl, 3, bl2, xl, br2, xr, bias2, out, 1);
    aggr_kernel<<<aggr_grid, 256>>>(xl, xr, att2, out);             // 11
}

// round 13
// speedup vs baseline: 1.7846x; 1.1008x over previous
#include <cuda_runtime.h>
#include <cuda_fp16.h>
#include <cstdint>

#define NN 100000
#define EE 640000
#define EP 740000            /* EE + NN self loops */
#define CC 128
#define NEG_SLOPE 0.2f
#define SCAN_BLK 1024
#define NBLK ((NN + SCAN_BLK - 1) / SCAN_BLK)   /* 98 */

// ---------------- device scratch ---------------------------------------------
__device__ __align__(16) __half g_xl[(size_t)NN * CC];   // fp16: halves gather traffic
__device__ __align__(16) __half g_xr[(size_t)NN * CC];
__device__ __align__(16) float  g_h [(size_t)NN * CC];
__device__ __align__(16) __half g_Wh[6 * CC * CC];  // weights hi (fp16)
__device__ __align__(16) __half g_Wl[6 * CC * CC];  // weights lo (fp16)
__device__ int   g_deg[NN];
__device__ int   g_cur[NN];
__device__ int   g_off[NN];
__device__ int   g_bsum[NBLK];
__device__ int   g_csr[EP];

// ---------------- weight pre-split (fp32 -> fp16 hi/lo) -----------------------
__global__ void wsplit_kernel(const float* __restrict__ W0, const float* __restrict__ W1,
                              const float* __restrict__ W2, const float* __restrict__ W3,
                              const float* __restrict__ W4, const float* __restrict__ W5)
{
    const float* Ws[6] = {W0, W1, W2, W3, W4, W5};
    int i = blockIdx.x * blockDim.x + threadIdx.x;
    if (i >= 6 * CC * CC) return;
    float v = Ws[i >> 14][i & 16383];
    __half h = __float2half_rn(v);
    __half l = __float2half_rn(v - __half2float(h));
    g_Wh[i] = h;
    g_Wl[i] = l;
}

// ---------------- CSR build ---------------------------------------------------
__global__ void hist_kernel(const int* __restrict__ ei) {
    int e = blockIdx.x * blockDim.x + threadIdx.x;
    if (e >= EP) return;
    int d = (e < EE) ? ei[EE + e] : (e - EE);
    atomicAdd(&g_deg[d], 1);
}

__global__ void scan1_kernel() {
    __shared__ int sh[SCAN_BLK];
    int i = blockIdx.x * SCAN_BLK + threadIdx.x;
    int v = (i < NN) ? g_deg[i] : 0;
    sh[threadIdx.x] = v;
    __syncthreads();
    for (int o = 1; o < SCAN_BLK; o <<= 1) {
        int t = (threadIdx.x >= o) ? sh[threadIdx.x - o] : 0;
        __syncthreads();
        sh[threadIdx.x] += t;
        __syncthreads();
    }
    if (i < NN) g_off[i] = sh[threadIdx.x] - v;
    if (threadIdx.x == SCAN_BLK - 1) g_bsum[blockIdx.x] = sh[threadIdx.x];
}

__global__ void scan2_kernel() {
    __shared__ int sh[128];
    int b = threadIdx.x;
    int v = (b < NBLK) ? g_bsum[b] : 0;
    sh[b] = v;
    __syncthreads();
    for (int o = 1; o < 128; o <<= 1) {
        int t = (b >= o) ? sh[b - o] : 0;
        __syncthreads();
        sh[b] += t;
        __syncthreads();
    }
    if (b < NBLK) g_bsum[b] = sh[b] - v;
}

__global__ void scan3_kernel() {
    int i = blockIdx.x * blockDim.x + threadIdx.x;
    if (i < NN) g_off[i] += g_bsum[i / SCAN_BLK];
}

__global__ void scatter_kernel(const int* __restrict__ ei) {
    int e = blockIdx.x * blockDim.x + threadIdx.x;
    if (e >= EP) return;
    int s, d;
    if (e < EE) { s = ei[e]; d = ei[EE + e]; }
    else        { s = d = e - EE; }
    int pos = g_off[d] + atomicAdd(&g_cur[d], 1);
    g_csr[pos] = s;
}

// ================= HMMA (mma.sync) 3-output GEMM ==============================
// fp16 2-term split (validated R12: rel_err 2.79e-4 == predicted 2.8e-4).
// D = Ah*Wh + Ah*Wl. 512 thr / 16 warps (4x4 of 32x32 tiles), cp.async
// double-buffered W. Outputs 0,1 (xl,xr scratch) stored as fp16 to halve
// the aggregation's gather traffic; output 2 (h/out) fp32.
#define AS_STRIDE 136                    /* fp16 units; LDSM rows 272B apart -> conflict-free */
#define TILE_B (128 * AS_STRIDE * 2)     /* 34816 bytes */
#define SM_AH  0
#define SM_BB  (TILE_B)                  /* B buffers: buf*(2*TILE_B) + {0:hi, TILE_B:lo} */
#define SM_TOTAL (5 * TILE_B)            /* 174080 = 170 KB */

__device__ __forceinline__ void mma16816(float* c, const uint32_t* a,
                                         const uint32_t* b) {
    asm volatile(
        "mma.sync.aligned.m16n8k16.row.col.f32.f16.f16.f32 "
        "{%0,%1,%2,%3}, {%4,%5,%6,%7}, {%8,%9}, {%0,%1,%2,%3};"
        : "+f"(c[0]), "+f"(c[1]), "+f"(c[2]), "+f"(c[3])
        : "r"(a[0]), "r"(a[1]), "r"(a[2]), "r"(a[3]), "r"(b[0]), "r"(b[1]));
}

__device__ __forceinline__ void ldsm_x4(uint32_t* r, uint32_t addr) {
    asm volatile("ldmatrix.sync.aligned.m8n8.x4.shared.b16 {%0,%1,%2,%3}, [%4];"
                 : "=r"(r[0]), "=r"(r[1]), "=r"(r[2]), "=r"(r[3]) : "r"(addr));
}

__device__ __forceinline__ void cp_async16(uint32_t dst, const void* src) {
    asm volatile("cp.async.cg.shared.global [%0], [%1], 16;"
                 :: "r"(dst), "l"(src));
}
#define CP_COMMIT() asm volatile("cp.async.commit_group;" ::: "memory")
#define CP_WAIT1()  asm volatile("cp.async.wait_group 1;" ::: "memory")
#define CP_WAIT0()  asm volatile("cp.async.wait_group 0;" ::: "memory")

// prefetch one pre-split W tile (hi+lo) into a B buffer via cp.async
__device__ __forceinline__ void prefetch_w(const __half* srch, const __half* srcl,
                                           uint32_t dsth, uint32_t dstl, int tid) {
#pragma unroll
    for (int t = 0; t < 4; t++) {
        int idx = tid + t * 512;         // 2048 x 16B per tile
        int row = idx >> 4;
        int k8  = (idx & 15) << 3;
        uint32_t off = (uint32_t)(row * AS_STRIDE + k8) * 2;
        cp_async16(dsth + off, srch + row * CC + k8);
        cp_async16(dstl + off, srcl + row * CC + k8);
    }
}

__global__ __launch_bounds__(512, 1) void gemm3_tc_kernel(
    const float* __restrict__ x,
    const __half* __restrict__ Wh, const __half* __restrict__ Wl,
    int mat0,
    const float* __restrict__ b0, __half* __restrict__ o0,
    const float* __restrict__ b1, __half* __restrict__ o1,
    const float* __restrict__ b2, float* __restrict__ o2,
    int relu_in)
{
    extern __shared__ char sm[];
    const int tid  = threadIdx.x;
    const int wid  = tid >> 5;
    const int lane = tid & 31;
    const int g    = lane >> 2;          // 0..7
    const int tg   = lane & 3;           // 0..3
    const int row0 = blockIdx.x * 128;
    const int nrows = (NN - row0 < 128) ? (NN - row0) : 128;
    const int wm0 = (wid >> 2) * 32;     // warp tile m origin (0/32/64/96)
    const int wn0 = (wid & 3) * 32;      // warp tile n origin (0/32/64/96)

    const uint32_t smb = (uint32_t)__cvta_generic_to_shared(sm);

    // prefetch B(0) immediately (overlaps with A conversion below)
    prefetch_w(Wh + (size_t)mat0 * CC * CC, Wl + (size_t)mat0 * CC * CC,
               smb + SM_BB, smb + SM_BB + TILE_B, tid);
    CP_COMMIT();

    // A tile -> fp16 (rounded); 4096 float4 over 512 threads
#pragma unroll
    for (int t = 0; t < 8; t++) {
        int idx = tid + t * 512;
        int row = idx >> 5;
        int k4  = (idx & 31) << 2;
        float4 v = make_float4(0.f, 0.f, 0.f, 0.f);
        if (row < nrows)
            v = *(const float4*)(x + (size_t)(row0 + row) * CC + k4);
        if (relu_in) {
            v.x = fmaxf(v.x, 0.f); v.y = fmaxf(v.y, 0.f);
            v.z = fmaxf(v.z, 0.f); v.w = fmaxf(v.w, 0.f);
        }
        __half2 p0 = __floats2half2_rn(v.x, v.y);
        __half2 p1 = __floats2half2_rn(v.z, v.w);
        uint32_t off = (uint32_t)(row * AS_STRIDE + k4) * 2;
        *(__half2*)(sm + SM_AH + off)     = p0;
        *(__half2*)(sm + SM_AH + off + 4) = p1;
    }

    // ldmatrix per-lane base addresses
    const uint32_t a_lane_off =
        (uint32_t)(((wm0 + (lane & 15)) * AS_STRIDE + ((lane >> 4) << 3)) * 2);
    const uint32_t ah_base = smb + SM_AH + a_lane_off;
    const int b_row = (lane & 7) + ((lane & 16) ? 8 : 0);
    const uint32_t b_lane_off =
        (uint32_t)(((wn0 + b_row) * AS_STRIDE + ((lane & 8) ? 8 : 0)) * 2);

    for (int j = 0; j < 3; j++) {
        if (j + 1 < 3) {                 // prefetch B(j+1) into alternate buffer
            uint32_t bb = smb + SM_BB + (uint32_t)(((j + 1) & 1) * 2 * TILE_B);
            prefetch_w(Wh + (size_t)(mat0 + j + 1) * CC * CC,
                       Wl + (size_t)(mat0 + j + 1) * CC * CC,
                       bb, bb + TILE_B, tid);
            CP_COMMIT();
            CP_WAIT1();                  // B(j) complete (one newer group pending)
        } else {
            CP_WAIT0();
        }
        __syncthreads();                 // B(j) visible; A visible (j==0)

        const uint32_t bbase = smb + SM_BB + (uint32_t)((j & 1) * 2 * TILE_B);
        const uint32_t bhi_base = bbase + b_lane_off;
        const uint32_t blo_base = bbase + TILE_B + b_lane_off;

        float acc[2][4][4];
#pragma unroll
        for (int ma = 0; ma < 2; ma++)
#pragma unroll
            for (int na = 0; na < 4; na++)
#pragma unroll
                for (int q = 0; q < 4; q++) acc[ma][na][q] = 0.f;

#pragma unroll
        for (int ks = 0; ks < 8; ks++) {
            const uint32_t kso = (uint32_t)(ks * 16 * 2);
            uint32_t bh[4][2], bl[4][2], af[2][4];
#pragma unroll
            for (int nap = 0; nap < 2; nap++) {
                uint32_t r[4];
                ldsm_x4(r, bhi_base + (uint32_t)(nap * 16 * AS_STRIDE * 2) + kso);
                bh[nap * 2][0] = r[0]; bh[nap * 2][1] = r[1];
                bh[nap * 2 + 1][0] = r[2]; bh[nap * 2 + 1][1] = r[3];
                ldsm_x4(r, blo_base + (uint32_t)(nap * 16 * AS_STRIDE * 2) + kso);
                bl[nap * 2][0] = r[0]; bl[nap * 2][1] = r[1];
                bl[nap * 2 + 1][0] = r[2]; bl[nap * 2 + 1][1] = r[3];
            }
#pragma unroll
            for (int ma = 0; ma < 2; ma++)
                ldsm_x4(af[ma], ah_base + (uint32_t)(ma * 16 * AS_STRIDE * 2) + kso);
#pragma unroll
            for (int ma = 0; ma < 2; ma++)
#pragma unroll
                for (int na = 0; na < 4; na++)
                    mma16816(acc[ma][na], af[ma], bh[na]);
#pragma unroll
            for (int ma = 0; ma < 2; ma++)
#pragma unroll
                for (int na = 0; na < 4; na++)
                    mma16816(acc[ma][na], af[ma], bl[na]);
        }

        // epilogue: bias + gmem stores. j=0,1 -> fp16 (xl/xr scratch); j=2 -> fp32.
        if (j < 2) {
            const float* bias = (j == 0) ? b0 : b1;
            __half* o = (j == 0) ? o0 : o1;
#pragma unroll
            for (int na = 0; na < 4; na++) {
                int col = wn0 + na * 8 + tg * 2;
                float2 bb2 = *(const float2*)(bias + col);
#pragma unroll
                for (int ma = 0; ma < 2; ma++) {
                    int ra = row0 + wm0 + ma * 16 + g;
                    if (ra < NN) {
                        *(__half2*)(o + (size_t)ra * CC + col) =
                            __floats2half2_rn(acc[ma][na][0] + bb2.x,
                                              acc[ma][na][1] + bb2.y);
                    }
                    int rb = ra + 8;
                    if (rb < NN) {
                        *(__half2*)(o + (size_t)rb * CC + col) =
                            __floats2half2_rn(acc[ma][na][2] + bb2.x,
                                              acc[ma][na][3] + bb2.y);
                    }
                }
            }
        } else {
#pragma unroll
            for (int na = 0; na < 4; na++) {
                int col = wn0 + na * 8 + tg * 2;
                float2 bb2 = *(const float2*)(b2 + col);
#pragma unroll
                for (int ma = 0; ma < 2; ma++) {
                    int ra = row0 + wm0 + ma * 16 + g;
                    if (ra < NN) {
                        float2 v = make_float2(acc[ma][na][0] + bb2.x,
                                               acc[ma][na][1] + bb2.y);
                        *(float2*)(o2 + (size_t)ra * CC + col) = v;
                    }
                    int rb = ra + 8;
                    if (rb < NN) {
                        float2 v = make_float2(acc[ma][na][2] + bb2.x,
                                               acc[ma][na][3] + bb2.y);
                        *(float2*)(o2 + (size_t)rb * CC + col) = v;
                    }
                }
            }
        }
        __syncthreads();                 // buf (j&1) consumed before j+2 prefetch
    }
}

// ---------------- fused attention + aggregation (warp per dst, no atomics) ---
// xl/xr stored fp16 (256B row gathers); all arithmetic fp32.
__device__ __forceinline__ float4 load_half_row4(const __half* base, size_t row,
                                                 int lane) {
    uint2 u = *(const uint2*)(base + row * CC + lane * 4);
    __half2 h0 = *(__half2*)&u.x;
    __half2 h1 = *(__half2*)&u.y;
    float2 f0 = __half22float2(h0);
    float2 f1 = __half22float2(h1);
    return make_float4(f0.x, f0.y, f1.x, f1.y);
}

__device__ __forceinline__ float leaky_dot(float4 a, float4 r, float4 t) {
    float4 m;
    m.x = a.x + r.x; m.x = m.x > 0.f ? m.x : NEG_SLOPE * m.x;
    m.y = a.y + r.y; m.y = m.y > 0.f ? m.y : NEG_SLOPE * m.y;
    m.z = a.z + r.z; m.z = m.z > 0.f ? m.z : NEG_SLOPE * m.z;
    m.w = a.w + r.w; m.w = m.w > 0.f ? m.w : NEG_SLOPE * m.w;
    float p = m.x * t.x;
    p = fmaf(m.y, t.y, p);
    p = fmaf(m.z, t.z, p);
    p = fmaf(m.w, t.w, p);
    return p;
}

__global__ __launch_bounds__(256) void aggr_kernel(
    const __half* __restrict__ xl, const __half* __restrict__ xr,
    const float* __restrict__ att, float* __restrict__ res_out)
{
    int gw   = (int)((blockIdx.x * 256u + threadIdx.x) >> 5);
    int lane = threadIdx.x & 31;
    if (gw >= NN) return;
    const int d = gw;

    float4 t = *(const float4*)(att + lane * 4);
    float4 r = load_half_row4(xr, (size_t)d, lane);

    const int start = g_off[d];
    const int deg   = g_deg[d];          // >= 1 (self loop)

    float denom = 0.f;
    float4 acc = make_float4(0.f, 0.f, 0.f, 0.f);

    int jj = 0;
    for (; jj + 1 < deg; jj += 2) {
        int s0 = g_csr[start + jj];
        int s1 = g_csr[start + jj + 1];
        float4 a0 = load_half_row4(xl, (size_t)s0, lane);
        float4 a1 = load_half_row4(xl, (size_t)s1, lane);
        float p0 = leaky_dot(a0, r, t);
        float p1 = leaky_dot(a1, r, t);
#pragma unroll
        for (int off = 16; off > 0; off >>= 1) {
            p0 += __shfl_xor_sync(0xffffffffu, p0, off);
            p1 += __shfl_xor_sync(0xffffffffu, p1, off);
        }
        float ev0 = expf(p0);
        float ev1 = expf(p1);
        denom += ev0 + ev1;
        acc.x = fmaf(ev0, a0.x, fmaf(ev1, a1.x, acc.x));
        acc.y = fmaf(ev0, a0.y, fmaf(ev1, a1.y, acc.y));
        acc.z = fmaf(ev0, a0.z, fmaf(ev1, a1.z, acc.z));
        acc.w = fmaf(ev0, a0.w, fmaf(ev1, a1.w, acc.w));
    }
    if (jj < deg) {
        int s0 = g_csr[start + jj];
        float4 a0 = load_half_row4(xl, (size_t)s0, lane);
        float p0 = leaky_dot(a0, r, t);
#pragma unroll
        for (int off = 16; off > 0; off >>= 1)
            p0 += __shfl_xor_sync(0xffffffffu, p0, off);
        float ev0 = expf(p0);
        denom += ev0;
        acc.x = fmaf(ev0, a0.x, acc.x);
        acc.y = fmaf(ev0, a0.y, acc.y);
        acc.z = fmaf(ev0, a0.z, acc.z);
        acc.w = fmaf(ev0, a0.w, acc.w);
    }

    float inv = 1.f / denom;
    float* op = res_out + (size_t)d * CC + lane * 4;
    float4 rr = *(const float4*)op;
    float4 o = make_float4(fmaf(acc.x, inv, rr.x), fmaf(acc.y, inv, rr.y),
                           fmaf(acc.z, inv, rr.z), fmaf(acc.w, inv, rr.w));
    *(float4*)op = o;
}

// ---------------- launch ------------------------------------------------------
extern "C" void kernel_launch(void* const* d_in, const int* in_sizes, int n_in,
                              void* d_out, int out_size)
{
    const int*   ei    = (const int*)  d_in[0];
    const float* emb   = (const float*)d_in[1];
    const float* Wl1   = (const float*)d_in[2];
    const float* bl1   = (const float*)d_in[3];
    const float* Wr1   = (const float*)d_in[4];
    const float* br1   = (const float*)d_in[5];
    const float* att1  = (const float*)d_in[6];
    const float* Wres1 = (const float*)d_in[7];
    const float* bias1 = (const float*)d_in[8];
    const float* Wl2   = (const float*)d_in[9];
    const float* bl2   = (const float*)d_in[10];
    const float* Wr2   = (const float*)d_in[11];
    const float* br2   = (const float*)d_in[12];
    const float* att2  = (const float*)d_in[13];
    const float* Wres2 = (const float*)d_in[14];
    const float* bias2 = (const float*)d_in[15];
    float* out = (float*)d_out;

    __half *xl, *xr, *Wh, *Wl;
    float *h;
    int *deg, *cur;
    cudaGetSymbolAddress((void**)&xl,  g_xl);
    cudaGetSymbolAddress((void**)&xr,  g_xr);
    cudaGetSymbolAddress((void**)&h,   g_h);
    cudaGetSymbolAddress((void**)&Wh,  g_Wh);
    cudaGetSymbolAddress((void**)&Wl,  g_Wl);
    cudaGetSymbolAddress((void**)&deg, g_deg);
    cudaGetSymbolAddress((void**)&cur, g_cur);

    cudaFuncSetAttribute(gemm3_tc_kernel,
                         cudaFuncAttributeMaxDynamicSharedMemorySize, SM_TOTAL);

    const int edge_grid = (EP + 255) / 256;        // 2891
    const int gemm_grid = (NN + 127) / 128;        // 782
    const int aggr_grid = (NN * 32 + 255) / 256;   // 12500

    // Launch order chosen so ncu (-s 5 -c 1, memsets count) captures gemm3_tc.
    cudaMemsetAsync(deg, 0, NN * sizeof(int));                      // 0
    cudaMemsetAsync(cur, 0, NN * sizeof(int));                      // 1
    wsplit_kernel<<<(6 * CC * CC + 255) / 256, 256>>>(              // 2
        Wl1, Wr1, Wres1, Wl2, Wr2, Wres2);
    hist_kernel<<<edge_grid, 256>>>(ei);                            // 3
    scan1_kernel<<<NBLK, SCAN_BLK>>>();                             // 4
    gemm3_tc_kernel<<<gemm_grid, 512, SM_TOTAL>>>(                  // 5  <- profiled
        emb, Wh, Wl, 0, bl1, xl, br1, xr, bias1, h, 0);
    scan2_kernel<<<1, 128>>>();                                     // 6
    scan3_kernel<<<(NN + 255) / 256, 256>>>();                      // 7
    scatter_kernel<<<edge_grid, 256>>>(ei);                         // 8
    aggr_kernel<<<aggr_grid, 256>>>(xl, xr, att1, h);               // 9
    gemm3_tc_kernel<<<gemm_grid, 512, SM_TOTAL>>>(                  // 10
        h, Wh, Wl, 3, bl2, xl, br2, xr, bias2, out, 1);
    aggr_kernel<<<aggr_grid, 256>>>(xl, xr, att2, out);             // 11
}